// round 1
// baseline (speedup 1.0000x reference)
#include <cuda_runtime.h>
#include <cstdint>

#define D1 4096
#define D2 4096
#define UV_LD 256           // row stride for U/V (padded, zero-filled)
#define ALPHA 300.0f

// ---------------- scratch (device globals; no allocation in kernel_launch) ---
__device__ int   g_rows[256];
__device__ int   g_cols[256];
__device__ float g_U[D1 * UV_LD];                  // U[k, t]  (t = 2j / 2j+1)
__device__ float g_V[D2 * UV_LD];                  // V[l, t]
__device__ float g_Wc[(size_t)D1 * (size_t)D2];    // combined weight [l, k]

// ---------------- decode E (handles int32 or int64 storage) ------------------
__global__ void decode_E_kernel(const unsigned int* __restrict__ ew, int nc) {
    if (blockIdx.x != 0 || threadIdx.x != 0) return;
    // int64 little-endian: every element's high word is 0 (values < 4096).
    unsigned int oddor = 0;
    for (int i = 0; i < nc; ++i) oddor |= ew[2 * i + 1];
    bool is64 = (oddor == 0u);
    for (int j = 0; j < nc; ++j) {
        if (is64) {
            g_rows[j] = (int)ew[4 * j];              // element j
            g_cols[j] = (int)ew[4 * (nc + j)];       // element nc+j
        } else {
            g_rows[j] = (int)ew[j];
            g_cols[j] = (int)ew[nc + j];
        }
    }
}

// ---------------- build U, V --------------------------------------------------
// U[k,2j]   =  c_j*s*cos(2*pi*a_j*k/D1),  U[k,2j+1] = -c_j*s*sin(...)
// V[l,2j]   =  cos(2*pi*b_j*l/D2),        V[l,2j+1] =  sin(...)
// => (U V^T)[k,l] = DeltaW[k,l] = s * sum_j c_j cos(2pi(a_j k/D1 + b_j l/D2))
__global__ void build_uv_kernel(const float* __restrict__ c, int nc, float scale) {
    int k   = blockIdx.x;          // row index (0..4095)
    int j   = threadIdx.x;         // 0..127 -> columns 2j, 2j+1
    bool isV = (blockIdx.y != 0);
    float* dst = (isV ? g_V : g_U) + (size_t)k * UV_LD;
    if (j < nc) {
        int f = isV ? g_cols[j] : g_rows[j];
        int p = (f * k) & (D1 - 1);                  // exact integer phase
        float ang = (float)p * (6.2831853071795864769f / (float)D1);
        float sn, cs;
        sincosf(ang, &sn, &cs);
        if (isV) {
            dst[2 * j]     = cs;
            dst[2 * j + 1] = sn;
        } else {
            float a = c[j] * scale;
            dst[2 * j]     =  a * cs;
            dst[2 * j + 1] = -a * sn;
        }
    } else {
        dst[2 * j]     = 0.f;
        dst[2 * j + 1] = 0.f;
    }
}

// ---------------- generic NT SGEMM: C[m,n] = sum_k A[m,k]*B[n,k] (+Add)(+bias)
// BM=BN=128, BK=8, 256 threads, 8x8 per-thread microtile.
// Requires: M,N multiples of 128; K multiple of 8; lda/ldb multiples of 4.
__global__ __launch_bounds__(256, 2)
void sgemm_nt_kernel(const float* __restrict__ A, int lda,
                     const float* __restrict__ B, int ldb,
                     float* __restrict__ C, int ldc,
                     int K,
                     const float* __restrict__ Add, int ldadd,
                     const float* __restrict__ bias) {
    __shared__ float As[8][128];
    __shared__ float Bs[8][128];

    const int m0 = blockIdx.y * 128;
    const int n0 = blockIdx.x * 128;
    const int t  = threadIdx.x;
    const int tx = t & 15;          // 0..15  -> n microtile
    const int ty = t >> 4;          // 0..15  -> m microtile

    // global-load mapping: 256 threads load 128 rows x 8 k (one float4 each)
    const int lrow = t >> 1;
    const int lk   = (t & 1) * 4;

    const float* Aptr = A + (size_t)(m0 + lrow) * lda + lk;
    const float* Bptr = B + (size_t)(n0 + lrow) * ldb + lk;

    float acc[8][8];
#pragma unroll
    for (int i = 0; i < 8; ++i)
#pragma unroll
        for (int j = 0; j < 8; ++j) acc[i][j] = 0.f;

    for (int k0 = 0; k0 < K; k0 += 8) {
        float4 a4 = *(const float4*)(Aptr + k0);
        float4 b4 = *(const float4*)(Bptr + k0);
        __syncthreads();                 // previous compute done before overwrite
        As[lk + 0][lrow] = a4.x;
        As[lk + 1][lrow] = a4.y;
        As[lk + 2][lrow] = a4.z;
        As[lk + 3][lrow] = a4.w;
        Bs[lk + 0][lrow] = b4.x;
        Bs[lk + 1][lrow] = b4.y;
        Bs[lk + 2][lrow] = b4.z;
        Bs[lk + 3][lrow] = b4.w;
        __syncthreads();

#pragma unroll
        for (int kk = 0; kk < 8; ++kk) {
            float4 a0 = *(const float4*)&As[kk][ty * 8];
            float4 a1 = *(const float4*)&As[kk][ty * 8 + 4];
            float4 b0 = *(const float4*)&Bs[kk][tx * 8];
            float4 b1 = *(const float4*)&Bs[kk][tx * 8 + 4];
            float av[8] = {a0.x, a0.y, a0.z, a0.w, a1.x, a1.y, a1.z, a1.w};
            float bv[8] = {b0.x, b0.y, b0.z, b0.w, b1.x, b1.y, b1.z, b1.w};
#pragma unroll
            for (int i = 0; i < 8; ++i)
#pragma unroll
                for (int j = 0; j < 8; ++j)
                    acc[i][j] += av[i] * bv[j];
        }
    }

    // epilogue: optional dense addend (same shape as C) and optional bias[n]
    float bvz[8];
    if (bias) {
        float4 c0 = *(const float4*)(bias + n0 + tx * 8);
        float4 c1 = *(const float4*)(bias + n0 + tx * 8 + 4);
        bvz[0]=c0.x; bvz[1]=c0.y; bvz[2]=c0.z; bvz[3]=c0.w;
        bvz[4]=c1.x; bvz[5]=c1.y; bvz[6]=c1.z; bvz[7]=c1.w;
    }
#pragma unroll
    for (int i = 0; i < 8; ++i) {
        int gm = m0 + ty * 8 + i;
        size_t cb = (size_t)gm * ldc + n0 + tx * 8;
        float v[8];
#pragma unroll
        for (int j = 0; j < 8; ++j) v[j] = acc[i][j];
        if (Add) {
            size_t ab = (size_t)gm * ldadd + n0 + tx * 8;
            float4 w0 = *(const float4*)(Add + ab);
            float4 w1 = *(const float4*)(Add + ab + 4);
            v[0]+=w0.x; v[1]+=w0.y; v[2]+=w0.z; v[3]+=w0.w;
            v[4]+=w1.x; v[5]+=w1.y; v[6]+=w1.z; v[7]+=w1.w;
        }
        if (bias) {
#pragma unroll
            for (int j = 0; j < 8; ++j) v[j] += bvz[j];
        }
        *(float4*)(C + cb)     = make_float4(v[0], v[1], v[2], v[3]);
        *(float4*)(C + cb + 4) = make_float4(v[4], v[5], v[6], v[7]);
    }
}

// -----------------------------------------------------------------------------
extern "C" void kernel_launch(void* const* d_in, const int* in_sizes, int n_in,
                              void* d_out, int out_size) {
    const float*        x = (const float*)d_in[0];
    const float*        c = (const float*)d_in[1];
    const unsigned int* E = (const unsigned int*)d_in[2];
    const float*        W = (const float*)d_in[3];
    const float*        b = (const float*)d_in[4];
    float*            out = (float*)d_out;

    int nc = in_sizes[1];                 // 100
    int M  = in_sizes[0] / D1;            // 8192

    float *U, *V, *Wc;
    cudaGetSymbolAddress((void**)&U,  g_U);
    cudaGetSymbolAddress((void**)&V,  g_V);
    cudaGetSymbolAddress((void**)&Wc, g_Wc);

    float scale = ALPHA / ((float)D1 * (float)D2);

    decode_E_kernel<<<1, 32>>>(E, nc);
    build_uv_kernel<<<dim3(D1, 2), 128>>>(c, nc, scale);

    // Wc[l,k] = sum_t V[l,t]*U[k,t] + W[l,k]      (M=4096, N=4096, K=2*nc)
    sgemm_nt_kernel<<<dim3(D1 / 128, D2 / 128), 256>>>(
        V, UV_LD, U, UV_LD, Wc, D1, 2 * nc, W, D1, nullptr);

    // out[m,l] = sum_k x[m,k]*Wc[l,k] + b[l]      (M=8192, N=4096, K=4096)
    sgemm_nt_kernel<<<dim3(D2 / 128, M / 128), 256>>>(
        x, D1, Wc, D1, out, D2, D1, nullptr, 0, b);
}

// round 3
// speedup vs baseline: 2.8745x; 2.8745x over previous
#include <cuda_runtime.h>
#include <cuda_bf16.h>
#include <cstdint>

#define D1 4096
#define D2 4096
#define KTOT 4096
#define UV_LD 256
#define ALPHA 300.0f

// ---- main GEMM tiling ----
#define BM 128
#define BN 128
#define BK 32
#define STAGES 4
#define RSB 80                        // padded row stride bytes (40 bf16)
#define CPY_BYTES (BM * RSB)          // 10240 per matrix copy
#define STG_BYTES (4 * CPY_BYTES)     // Ahi,Alo,Bhi,Blo = 40960
#define SMEM_MAIN (STAGES * STG_BYTES)
#define NCH (KTOT / BK)               // 128

// ---------------- device globals (scratch) -----------------------------------
__device__ int   g_rows[256];
__device__ int   g_cols[256];
__device__ float g_U[D1 * UV_LD];
__device__ float g_V[D2 * UV_LD];
__device__ __nv_bfloat16 g_Wh[(size_t)D2 * D1];
__device__ __nv_bfloat16 g_Wl[(size_t)D2 * D1];
__device__ __nv_bfloat16 g_Xh[(size_t)8192 * D1];
__device__ __nv_bfloat16 g_Xl[(size_t)8192 * D1];

// ---------------- PTX helpers (portable, sm_80-era) ---------------------------
__device__ __forceinline__ uint32_t smem_u32(const void* p) {
    uint32_t a;
    asm("{ .reg .u64 t; cvta.to.shared.u64 t, %1; cvt.u32.u64 %0, t; }" : "=r"(a) : "l"(p));
    return a;
}
__device__ __forceinline__ void cpa16(uint32_t d, const void* s) {
    asm volatile("cp.async.cg.shared.global [%0], [%1], 16;"
                 :: "r"(d), "l"(__cvta_generic_to_global(s)) : "memory");
}
__device__ __forceinline__ void ldsm4(uint32_t* r, uint32_t addr) {
    asm volatile("ldmatrix.sync.aligned.m8n8.x4.shared.b16 {%0,%1,%2,%3}, [%4];"
                 : "=r"(r[0]), "=r"(r[1]), "=r"(r[2]), "=r"(r[3]) : "r"(addr));
}
__device__ __forceinline__ void mma16816(float* c, const uint32_t* a, const uint32_t* b) {
    asm volatile(
        "mma.sync.aligned.m16n8k16.row.col.f32.bf16.bf16.f32 "
        "{%0,%1,%2,%3}, {%4,%5,%6,%7}, {%8,%9}, {%0,%1,%2,%3};"
        : "+f"(c[0]), "+f"(c[1]), "+f"(c[2]), "+f"(c[3])
        : "r"(a[0]), "r"(a[1]), "r"(a[2]), "r"(a[3]), "r"(b[0]), "r"(b[1]));
}

// ---------------- decode E (int32 or int64 storage) ---------------------------
__global__ void decode_E_kernel(const unsigned int* __restrict__ ew, int nc) {
    if (threadIdx.x != 0) return;
    unsigned int oddor = 0;
    for (int i = 0; i < nc; ++i) oddor |= ew[2 * i + 1];
    bool is64 = (oddor == 0u);
    for (int j = 0; j < nc; ++j) {
        if (is64) { g_rows[j] = (int)ew[4 * j]; g_cols[j] = (int)ew[4 * (nc + j)]; }
        else      { g_rows[j] = (int)ew[j];     g_cols[j] = (int)ew[nc + j]; }
    }
}

// ---------------- build U, V ---------------------------------------------------
__global__ void build_uv_kernel(const float* __restrict__ c, int nc, float scale) {
    int k = blockIdx.x, j = threadIdx.x;
    bool isV = (blockIdx.y != 0);
    float* dst = (isV ? g_V : g_U) + (size_t)k * UV_LD;
    if (j < nc) {
        int f = isV ? g_cols[j] : g_rows[j];
        int p = (f * k) & (D1 - 1);
        float ang = (float)p * (6.2831853071795864769f / (float)D1);
        float sn, cs;
        sincosf(ang, &sn, &cs);
        if (isV) { dst[2 * j] = cs; dst[2 * j + 1] = sn; }
        else {
            float a = c[j] * scale;
            dst[2 * j] = a * cs; dst[2 * j + 1] = -a * sn;
        }
    } else { dst[2 * j] = 0.f; dst[2 * j + 1] = 0.f; }
}

// ---------------- fp32 NT GEMM: Wc = V U^T + W_base, split to bf16 hi/lo -------
__global__ __launch_bounds__(256, 2)
void sgemm_uv_kernel(const float* __restrict__ A, int lda,
                     const float* __restrict__ B, int ldb,
                     __nv_bfloat16* __restrict__ Chi,
                     __nv_bfloat16* __restrict__ Clo,
                     int ldc, int K, const float* __restrict__ Add, int ldadd) {
    __shared__ float As[8][128];
    __shared__ float Bs[8][128];
    const int m0 = blockIdx.y * 128, n0 = blockIdx.x * 128;
    const int t = threadIdx.x, tx = t & 15, ty = t >> 4;
    const int lrow = t >> 1, lk = (t & 1) * 4;
    const float* Aptr = A + (size_t)(m0 + lrow) * lda + lk;
    const float* Bptr = B + (size_t)(n0 + lrow) * ldb + lk;

    float acc[8][8];
#pragma unroll
    for (int i = 0; i < 8; ++i)
#pragma unroll
        for (int j = 0; j < 8; ++j) acc[i][j] = 0.f;

    for (int k0 = 0; k0 < K; k0 += 8) {
        float4 a4 = *(const float4*)(Aptr + k0);
        float4 b4 = *(const float4*)(Bptr + k0);
        __syncthreads();
        As[lk+0][lrow]=a4.x; As[lk+1][lrow]=a4.y; As[lk+2][lrow]=a4.z; As[lk+3][lrow]=a4.w;
        Bs[lk+0][lrow]=b4.x; Bs[lk+1][lrow]=b4.y; Bs[lk+2][lrow]=b4.z; Bs[lk+3][lrow]=b4.w;
        __syncthreads();
#pragma unroll
        for (int kk = 0; kk < 8; ++kk) {
            float4 a0 = *(const float4*)&As[kk][ty*8];
            float4 a1 = *(const float4*)&As[kk][ty*8+4];
            float4 b0 = *(const float4*)&Bs[kk][tx*8];
            float4 b1 = *(const float4*)&Bs[kk][tx*8+4];
            float av[8]={a0.x,a0.y,a0.z,a0.w,a1.x,a1.y,a1.z,a1.w};
            float bv[8]={b0.x,b0.y,b0.z,b0.w,b1.x,b1.y,b1.z,b1.w};
#pragma unroll
            for (int i = 0; i < 8; ++i)
#pragma unroll
                for (int j = 0; j < 8; ++j) acc[i][j] += av[i]*bv[j];
        }
    }
#pragma unroll
    for (int i = 0; i < 8; ++i) {
        int gm = m0 + ty*8 + i;
        size_t ab = (size_t)gm * ldadd + n0 + tx*8;
        float4 w0 = *(const float4*)(Add + ab);
        float4 w1 = *(const float4*)(Add + ab + 4);
        float v[8] = {acc[i][0]+w0.x, acc[i][1]+w0.y, acc[i][2]+w0.z, acc[i][3]+w0.w,
                      acc[i][4]+w1.x, acc[i][5]+w1.y, acc[i][6]+w1.z, acc[i][7]+w1.w};
        __align__(16) __nv_bfloat16 hv[8], lv[8];
#pragma unroll
        for (int j = 0; j < 8; ++j) {
            hv[j] = __float2bfloat16_rn(v[j]);
            lv[j] = __float2bfloat16_rn(v[j] - __bfloat162float(hv[j]));
        }
        size_t cb = (size_t)gm * ldc + n0 + tx*8;
        *(uint4*)(Chi + cb) = *(const uint4*)hv;
        *(uint4*)(Clo + cb) = *(const uint4*)lv;
    }
}

// ---------------- split x into bf16 hi/lo -------------------------------------
__global__ void split_kernel(const float* __restrict__ s,
                             __nv_bfloat16* __restrict__ h,
                             __nv_bfloat16* __restrict__ l, size_t n4) {
    size_t i = blockIdx.x * (size_t)blockDim.x + threadIdx.x;
    if (i >= n4) return;
    float4 v = ((const float4*)s)[i];
    __align__(8) __nv_bfloat16 hv[4], lv[4];
    float vv[4] = {v.x, v.y, v.z, v.w};
#pragma unroll
    for (int j = 0; j < 4; ++j) {
        hv[j] = __float2bfloat16_rn(vv[j]);
        lv[j] = __float2bfloat16_rn(vv[j] - __bfloat162float(hv[j]));
    }
    ((uint2*)h)[i] = *(const uint2*)hv;
    ((uint2*)l)[i] = *(const uint2*)lv;
}

// ---------------- main GEMM: out = (Xh+Xl)(Wh+Wl)^T + b  (bf16x3, mma.sync) ---
__global__ void __launch_bounds__(256, 1)
gemm_mma_kernel(const __nv_bfloat16* __restrict__ Xh,
                const __nv_bfloat16* __restrict__ Xl,
                const __nv_bfloat16* __restrict__ Wh,
                const __nv_bfloat16* __restrict__ Wl,
                const float* __restrict__ bias,
                float* __restrict__ out) {
    extern __shared__ __align__(128) char smem[];
    const uint32_t sb = smem_u32(smem);
    const int tid  = threadIdx.x;
    const int lane = tid & 31;
    const int wid  = tid >> 5;
    const int wm   = wid >> 2;          // 0..1 -> 64 rows each
    const int wn   = wid & 3;           // 0..3 -> 32 cols each
    const int m0   = blockIdx.y * BM;
    const int n0   = blockIdx.x * BN;

    // cp.async mapping: per copy, 512 segs (128 rows x 4 x 16B); 2 per thread
    const int r0 = tid >> 2, s0 = tid & 3;           // seg idx tid
    const int r1 = (tid + 256) >> 2, s1 = (tid + 256) & 3;

    auto load_chunk = [&](int stg, int chunk) {
        const uint32_t base = sb + stg * STG_BYTES;
        const int kc = chunk * BK;
        {
            uint32_t so = (uint32_t)(r0 * RSB + s0 * 16);
            size_t gA = (size_t)(m0 + r0) * KTOT + kc + s0 * 8;
            size_t gB = (size_t)(n0 + r0) * KTOT + kc + s0 * 8;
            cpa16(base + 0 * CPY_BYTES + so, Xh + gA);
            cpa16(base + 1 * CPY_BYTES + so, Xl + gA);
            cpa16(base + 2 * CPY_BYTES + so, Wh + gB);
            cpa16(base + 3 * CPY_BYTES + so, Wl + gB);
        }
        {
            uint32_t so = (uint32_t)(r1 * RSB + s1 * 16);
            size_t gA = (size_t)(m0 + r1) * KTOT + kc + s1 * 8;
            size_t gB = (size_t)(n0 + r1) * KTOT + kc + s1 * 8;
            cpa16(base + 0 * CPY_BYTES + so, Xh + gA);
            cpa16(base + 1 * CPY_BYTES + so, Xl + gA);
            cpa16(base + 2 * CPY_BYTES + so, Wh + gB);
            cpa16(base + 3 * CPY_BYTES + so, Wl + gB);
        }
    };

    // ldmatrix per-lane base offsets (bytes within one matrix copy)
    // A tiles: lane groups -> rows 0-7 / 8-15 at k0 / k0+8
    const int a_row = (lane & 7) + ((lane >> 3) & 1) * 8;
    const int a_col = ((lane >> 4) & 1) * 8;
    const uint32_t a_off = (uint32_t)((wm * 64 + a_row) * RSB + a_col * 2);
    // B tiles: r0=b0(n0-7), r1=b1(n0-7), r2=b0(n8-15), r3=b1(n8-15)
    const int b_row = (lane & 7) + ((lane >> 4) & 1) * 8;    // n within 16
    const int b_col = ((lane >> 3) & 1) * 8;                 // k offset 0/8
    const uint32_t b_off = (uint32_t)((wn * 32 + b_row) * RSB + b_col * 2);

    float acc[4][4][4];
#pragma unroll
    for (int i = 0; i < 4; ++i)
#pragma unroll
        for (int j = 0; j < 4; ++j)
#pragma unroll
            for (int q = 0; q < 4; ++q) acc[i][j][q] = 0.f;

    // prologue: stages 0..STAGES-2
#pragma unroll
    for (int s = 0; s < STAGES - 1; ++s) {
        load_chunk(s, s);
        asm volatile("cp.async.commit_group;" ::: "memory");
    }

    for (int it = 0; it < NCH; ++it) {
        asm volatile("cp.async.wait_group %0;" :: "n"(STAGES - 2) : "memory");
        __syncthreads();

        // issue next chunk into the stage freed last iteration
        if (it + STAGES - 1 < NCH) load_chunk((it + STAGES - 1) % STAGES, it + STAGES - 1);
        asm volatile("cp.async.commit_group;" ::: "memory");

        const uint32_t st = sb + (it % STAGES) * STG_BYTES;
#pragma unroll
        for (int kk = 0; kk < 2; ++kk) {
            uint32_t ah[4][4], al[4][4], bh[4][2], bl[4][2];
#pragma unroll
            for (int i = 0; i < 4; ++i) {
                ldsm4(ah[i], st + 0 * CPY_BYTES + a_off + i * (16 * RSB) + kk * 32);
                ldsm4(al[i], st + 1 * CPY_BYTES + a_off + i * (16 * RSB) + kk * 32);
            }
#pragma unroll
            for (int j = 0; j < 2; ++j) {
                uint32_t t4[4];
                ldsm4(t4, st + 2 * CPY_BYTES + b_off + j * (16 * RSB) + kk * 32);
                bh[2*j][0] = t4[0]; bh[2*j][1] = t4[1];
                bh[2*j+1][0] = t4[2]; bh[2*j+1][1] = t4[3];
                ldsm4(t4, st + 3 * CPY_BYTES + b_off + j * (16 * RSB) + kk * 32);
                bl[2*j][0] = t4[0]; bl[2*j][1] = t4[1];
                bl[2*j+1][0] = t4[2]; bl[2*j+1][1] = t4[3];
            }
#pragma unroll
            for (int i = 0; i < 4; ++i)
#pragma unroll
                for (int j = 0; j < 4; ++j) {
                    mma16816(acc[i][j], ah[i], bh[j]);
                    mma16816(acc[i][j], ah[i], bl[j]);
                    mma16816(acc[i][j], al[i], bh[j]);
                }
        }
    }

    // epilogue
    const int col_base = n0 + wn * 32 + 2 * (lane & 3);
    float2 bj[4];
#pragma unroll
    for (int j = 0; j < 4; ++j) {
        bj[j].x = __ldg(bias + col_base + j * 8);
        bj[j].y = __ldg(bias + col_base + j * 8 + 1);
    }
    const int row_base = m0 + wm * 64 + (lane >> 2);
#pragma unroll
    for (int i = 0; i < 4; ++i) {
#pragma unroll
        for (int j = 0; j < 4; ++j) {
            size_t o0 = (size_t)(row_base + i * 16) * D2 + col_base + j * 8;
            size_t o1 = o0 + 8 * D2;
            float2 v0 = make_float2(acc[i][j][0] + bj[j].x, acc[i][j][1] + bj[j].y);
            float2 v1 = make_float2(acc[i][j][2] + bj[j].x, acc[i][j][3] + bj[j].y);
            *(float2*)(out + o0) = v0;
            *(float2*)(out + o1) = v1;
        }
    }
}

// -----------------------------------------------------------------------------
extern "C" void kernel_launch(void* const* d_in, const int* in_sizes, int n_in,
                              void* d_out, int out_size) {
    const float*        x = (const float*)d_in[0];
    const float*        c = (const float*)d_in[1];
    const unsigned int* E = (const unsigned int*)d_in[2];
    const float*        W = (const float*)d_in[3];
    const float*        b = (const float*)d_in[4];
    float*            out = (float*)d_out;

    int nc = in_sizes[1];
    int M  = in_sizes[0] / D1;      // 8192

    float *U, *V;
    __nv_bfloat16 *Wh, *Wl, *Xh, *Xl;
    cudaGetSymbolAddress((void**)&U,  g_U);
    cudaGetSymbolAddress((void**)&V,  g_V);
    cudaGetSymbolAddress((void**)&Wh, g_Wh);
    cudaGetSymbolAddress((void**)&Wl, g_Wl);
    cudaGetSymbolAddress((void**)&Xh, g_Xh);
    cudaGetSymbolAddress((void**)&Xl, g_Xl);

    float scale = ALPHA / ((float)D1 * (float)D2);

    decode_E_kernel<<<1, 32>>>(E, nc);
    build_uv_kernel<<<dim3(D1, 2), 128>>>(c, nc, scale);

    sgemm_uv_kernel<<<dim3(D1 / 128, D2 / 128), 256>>>(
        V, UV_LD, U, UV_LD, Wh, Wl, D1, 2 * nc, W, D1);

    size_t n4 = (size_t)M * D1 / 4;
    split_kernel<<<(unsigned)((n4 + 255) / 256), 256>>>(x, Xh, Xl, n4);

    cudaFuncSetAttribute(gemm_mma_kernel,
                         cudaFuncAttributeMaxDynamicSharedMemorySize, SMEM_MAIN);
    gemm_mma_kernel<<<dim3(D2 / BN, M / BM), 256, SMEM_MAIN>>>(
        Xh, Xl, Wh, Wl, b, out);
}

// round 4
// speedup vs baseline: 2.9034x; 1.0101x over previous
#include <cuda_runtime.h>
#include <cuda_bf16.h>
#include <cstdint>

#define D1 4096
#define D2 4096
#define KTOT 4096
#define UV_LD 256
#define ALPHA 300.0f

// ---- main GEMM tiling ----
#define BM 256
#define BN 128
#define BK 32
#define STAGES 3
#define RSB 80                          // padded row stride bytes (40 bf16)
#define AH_OFF 0
#define AL_OFF (BM * RSB)               // 20480
#define BH_OFF (2 * BM * RSB)           // 40960
#define BL_OFF (2 * BM * RSB + BN * RSB)
#define STG_BYTES ((2 * BM + 2 * BN) * RSB)   // 61440
#define SMEM_MAIN (STAGES * STG_BYTES)        // 184320
#define NCH (KTOT / BK)                 // 128

// ---------------- device globals (scratch) -----------------------------------
__device__ int   g_rows[256];
__device__ int   g_cols[256];
__device__ float g_U[D1 * UV_LD];
__device__ float g_V[D2 * UV_LD];
__device__ __nv_bfloat16 g_Wh[(size_t)D2 * D1];
__device__ __nv_bfloat16 g_Wl[(size_t)D2 * D1];
__device__ __nv_bfloat16 g_Xh[(size_t)8192 * D1];
__device__ __nv_bfloat16 g_Xl[(size_t)8192 * D1];

// ---------------- PTX helpers (portable, sm_80-era) ---------------------------
__device__ __forceinline__ uint32_t smem_u32(const void* p) {
    uint32_t a;
    asm("{ .reg .u64 t; cvta.to.shared.u64 t, %1; cvt.u32.u64 %0, t; }" : "=r"(a) : "l"(p));
    return a;
}
__device__ __forceinline__ void cpa16(uint32_t d, const void* s) {
    asm volatile("cp.async.cg.shared.global [%0], [%1], 16;"
                 :: "r"(d), "l"(__cvta_generic_to_global(s)) : "memory");
}
__device__ __forceinline__ void ldsm4(uint32_t* r, uint32_t addr) {
    asm volatile("ldmatrix.sync.aligned.m8n8.x4.shared.b16 {%0,%1,%2,%3}, [%4];"
                 : "=r"(r[0]), "=r"(r[1]), "=r"(r[2]), "=r"(r[3]) : "r"(addr));
}
__device__ __forceinline__ void mma16816(float* c, const uint32_t* a, const uint32_t* b) {
    asm volatile(
        "mma.sync.aligned.m16n8k16.row.col.f32.bf16.bf16.f32 "
        "{%0,%1,%2,%3}, {%4,%5,%6,%7}, {%8,%9}, {%0,%1,%2,%3};"
        : "+f"(c[0]), "+f"(c[1]), "+f"(c[2]), "+f"(c[3])
        : "r"(a[0]), "r"(a[1]), "r"(a[2]), "r"(a[3]), "r"(b[0]), "r"(b[1]));
}

// ---------------- decode E (int32 or int64 storage) ---------------------------
__global__ void decode_E_kernel(const unsigned int* __restrict__ ew, int nc) {
    if (threadIdx.x != 0) return;
    unsigned int oddor = 0;
    for (int i = 0; i < nc; ++i) oddor |= ew[2 * i + 1];
    bool is64 = (oddor == 0u);
    for (int j = 0; j < nc; ++j) {
        if (is64) { g_rows[j] = (int)ew[4 * j]; g_cols[j] = (int)ew[4 * (nc + j)]; }
        else      { g_rows[j] = (int)ew[j];     g_cols[j] = (int)ew[nc + j]; }
    }
}

// ---------------- build U, V ---------------------------------------------------
__global__ void build_uv_kernel(const float* __restrict__ c, int nc, float scale) {
    int k = blockIdx.x, j = threadIdx.x;
    bool isV = (blockIdx.y != 0);
    float* dst = (isV ? g_V : g_U) + (size_t)k * UV_LD;
    if (j < nc) {
        int f = isV ? g_cols[j] : g_rows[j];
        int p = (f * k) & (D1 - 1);
        float ang = (float)p * (6.2831853071795864769f / (float)D1);
        float sn, cs;
        sincosf(ang, &sn, &cs);
        if (isV) { dst[2 * j] = cs; dst[2 * j + 1] = sn; }
        else {
            float a = c[j] * scale;
            dst[2 * j] = a * cs; dst[2 * j + 1] = -a * sn;
        }
    } else { dst[2 * j] = 0.f; dst[2 * j + 1] = 0.f; }
}

// ---------------- fp32 NT GEMM: Wc = V U^T + W_base, split to bf16 hi/lo -------
__global__ __launch_bounds__(256, 2)
void sgemm_uv_kernel(const float* __restrict__ A, int lda,
                     const float* __restrict__ B, int ldb,
                     __nv_bfloat16* __restrict__ Chi,
                     __nv_bfloat16* __restrict__ Clo,
                     int ldc, int K, const float* __restrict__ Add, int ldadd) {
    __shared__ float As[8][128];
    __shared__ float Bs[8][128];
    const int m0 = blockIdx.y * 128, n0 = blockIdx.x * 128;
    const int t = threadIdx.x, tx = t & 15, ty = t >> 4;
    const int lrow = t >> 1, lk = (t & 1) * 4;
    const float* Aptr = A + (size_t)(m0 + lrow) * lda + lk;
    const float* Bptr = B + (size_t)(n0 + lrow) * ldb + lk;

    float acc[8][8];
#pragma unroll
    for (int i = 0; i < 8; ++i)
#pragma unroll
        for (int j = 0; j < 8; ++j) acc[i][j] = 0.f;

    for (int k0 = 0; k0 < K; k0 += 8) {
        float4 a4 = *(const float4*)(Aptr + k0);
        float4 b4 = *(const float4*)(Bptr + k0);
        __syncthreads();
        As[lk+0][lrow]=a4.x; As[lk+1][lrow]=a4.y; As[lk+2][lrow]=a4.z; As[lk+3][lrow]=a4.w;
        Bs[lk+0][lrow]=b4.x; Bs[lk+1][lrow]=b4.y; Bs[lk+2][lrow]=b4.z; Bs[lk+3][lrow]=b4.w;
        __syncthreads();
#pragma unroll
        for (int kk = 0; kk < 8; ++kk) {
            float4 a0 = *(const float4*)&As[kk][ty*8];
            float4 a1 = *(const float4*)&As[kk][ty*8+4];
            float4 b0 = *(const float4*)&Bs[kk][tx*8];
            float4 b1 = *(const float4*)&Bs[kk][tx*8+4];
            float av[8]={a0.x,a0.y,a0.z,a0.w,a1.x,a1.y,a1.z,a1.w};
            float bv[8]={b0.x,b0.y,b0.z,b0.w,b1.x,b1.y,b1.z,b1.w};
#pragma unroll
            for (int i = 0; i < 8; ++i)
#pragma unroll
                for (int j = 0; j < 8; ++j) acc[i][j] += av[i]*bv[j];
        }
    }
#pragma unroll
    for (int i = 0; i < 8; ++i) {
        int gm = m0 + ty*8 + i;
        size_t ab = (size_t)gm * ldadd + n0 + tx*8;
        float4 w0 = *(const float4*)(Add + ab);
        float4 w1 = *(const float4*)(Add + ab + 4);
        float v[8] = {acc[i][0]+w0.x, acc[i][1]+w0.y, acc[i][2]+w0.z, acc[i][3]+w0.w,
                      acc[i][4]+w1.x, acc[i][5]+w1.y, acc[i][6]+w1.z, acc[i][7]+w1.w};
        __align__(16) __nv_bfloat16 hv[8], lv[8];
#pragma unroll
        for (int j = 0; j < 8; ++j) {
            hv[j] = __float2bfloat16_rn(v[j]);
            lv[j] = __float2bfloat16_rn(v[j] - __bfloat162float(hv[j]));
        }
        size_t cb = (size_t)gm * ldc + n0 + tx*8;
        *(uint4*)(Chi + cb) = *(const uint4*)hv;
        *(uint4*)(Clo + cb) = *(const uint4*)lv;
    }
}

// ---------------- split x into bf16 hi/lo -------------------------------------
__global__ void split_kernel(const float* __restrict__ s,
                             __nv_bfloat16* __restrict__ h,
                             __nv_bfloat16* __restrict__ l, size_t n4) {
    size_t i = blockIdx.x * (size_t)blockDim.x + threadIdx.x;
    if (i >= n4) return;
    float4 v = ((const float4*)s)[i];
    __align__(8) __nv_bfloat16 hv[4], lv[4];
    float vv[4] = {v.x, v.y, v.z, v.w};
#pragma unroll
    for (int j = 0; j < 4; ++j) {
        hv[j] = __float2bfloat16_rn(vv[j]);
        lv[j] = __float2bfloat16_rn(vv[j] - __bfloat162float(hv[j]));
    }
    ((uint2*)h)[i] = *(const uint2*)hv;
    ((uint2*)l)[i] = *(const uint2*)lv;
}

// ---------------- main GEMM: out = (Xh+Xl)(Wh+Wl)^T + b  (bf16x3, mma.sync) ---
// CTA 256x128x32, 3-stage cp.async, 8 warps in 4x2 -> warp tile 64x64
__global__ void __launch_bounds__(256, 1)
gemm_mma_kernel(const __nv_bfloat16* __restrict__ Xh,
                const __nv_bfloat16* __restrict__ Xl,
                const __nv_bfloat16* __restrict__ Wh,
                const __nv_bfloat16* __restrict__ Wl,
                const float* __restrict__ bias,
                float* __restrict__ out) {
    extern __shared__ __align__(128) char smem[];
    const uint32_t sb = smem_u32(smem);
    const int tid  = threadIdx.x;
    const int lane = tid & 31;
    const int wid  = tid >> 5;
    const int wm   = wid & 3;           // 0..3 -> 64 rows each
    const int wn   = wid >> 2;          // 0..1 -> 64 cols each
    const int m0   = blockIdx.y * BM;
    const int n0   = blockIdx.x * BN;

    auto load_chunk = [&](int stg, int chunk) {
        const uint32_t base = sb + stg * STG_BYTES;
        const int kc = chunk * BK;
        // A: 256 rows x 4 segs of 16B, hi+lo  (4 iters x 256 threads)
#pragma unroll
        for (int it = 0; it < 4; ++it) {
            int idx = it * 256 + tid;
            int row = idx >> 2, seg = idx & 3;
            uint32_t so = (uint32_t)(row * RSB + seg * 16);
            size_t g = (size_t)(m0 + row) * KTOT + kc + seg * 8;
            cpa16(base + AH_OFF + so, Xh + g);
            cpa16(base + AL_OFF + so, Xl + g);
        }
        // B: 128 rows x 4 segs, hi+lo  (2 iters)
#pragma unroll
        for (int it = 0; it < 2; ++it) {
            int idx = it * 256 + tid;
            int row = idx >> 2, seg = idx & 3;
            uint32_t so = (uint32_t)(row * RSB + seg * 16);
            size_t g = (size_t)(n0 + row) * KTOT + kc + seg * 8;
            cpa16(base + BH_OFF + so, Wh + g);
            cpa16(base + BL_OFF + so, Wl + g);
        }
    };

    // ldmatrix per-lane offsets
    const int a_row = (lane & 7) + ((lane >> 3) & 1) * 8;
    const int a_col = ((lane >> 4) & 1) * 8;
    const uint32_t a_off = (uint32_t)((wm * 64 + a_row) * RSB + a_col * 2);
    const int b_row = (lane & 7) + ((lane >> 4) & 1) * 8;
    const int b_col = ((lane >> 3) & 1) * 8;
    const uint32_t b_off = (uint32_t)((wn * 64 + b_row) * RSB + b_col * 2);

    float acc[4][8][4];
#pragma unroll
    for (int i = 0; i < 4; ++i)
#pragma unroll
        for (int j = 0; j < 8; ++j)
#pragma unroll
            for (int q = 0; q < 4; ++q) acc[i][j][q] = 0.f;

#pragma unroll
    for (int s = 0; s < STAGES - 1; ++s) {
        load_chunk(s, s);
        asm volatile("cp.async.commit_group;" ::: "memory");
    }

    for (int it = 0; it < NCH; ++it) {
        asm volatile("cp.async.wait_group %0;" :: "n"(STAGES - 2) : "memory");
        __syncthreads();

        if (it + STAGES - 1 < NCH) load_chunk((it + STAGES - 1) % STAGES, it + STAGES - 1);
        asm volatile("cp.async.commit_group;" ::: "memory");

        const uint32_t st = sb + (it % STAGES) * STG_BYTES;
#pragma unroll
        for (int kk = 0; kk < 2; ++kk) {
            uint32_t ah[4][4], al[4][4], bh[8][2], bl[8][2];
#pragma unroll
            for (int i = 0; i < 4; ++i) {
                ldsm4(ah[i], st + AH_OFF + a_off + i * (16 * RSB) + kk * 32);
                ldsm4(al[i], st + AL_OFF + a_off + i * (16 * RSB) + kk * 32);
            }
#pragma unroll
            for (int j = 0; j < 4; ++j) {
                uint32_t t4[4];
                ldsm4(t4, st + BH_OFF + b_off + j * (16 * RSB) + kk * 32);
                bh[2*j][0] = t4[0]; bh[2*j][1] = t4[1];
                bh[2*j+1][0] = t4[2]; bh[2*j+1][1] = t4[3];
                ldsm4(t4, st + BL_OFF + b_off + j * (16 * RSB) + kk * 32);
                bl[2*j][0] = t4[0]; bl[2*j][1] = t4[1];
                bl[2*j+1][0] = t4[2]; bl[2*j+1][1] = t4[3];
            }
#pragma unroll
            for (int i = 0; i < 4; ++i)
#pragma unroll
                for (int j = 0; j < 8; ++j) {
                    mma16816(acc[i][j], ah[i], bh[j]);
                    mma16816(acc[i][j], ah[i], bl[j]);
                    mma16816(acc[i][j], al[i], bh[j]);
                }
        }
    }

    // epilogue
    const int col_base = n0 + wn * 64 + 2 * (lane & 3);
    float2 bj[8];
#pragma unroll
    for (int j = 0; j < 8; ++j) {
        bj[j].x = __ldg(bias + col_base + j * 8);
        bj[j].y = __ldg(bias + col_base + j * 8 + 1);
    }
    const int row_base = m0 + wm * 64 + (lane >> 2);
#pragma unroll
    for (int i = 0; i < 4; ++i) {
#pragma unroll
        for (int j = 0; j < 8; ++j) {
            size_t o0 = (size_t)(row_base + i * 16) * D2 + col_base + j * 8;
            size_t o1 = o0 + 8 * D2;
            float2 v0 = make_float2(acc[i][j][0] + bj[j].x, acc[i][j][1] + bj[j].y);
            float2 v1 = make_float2(acc[i][j][2] + bj[j].x, acc[i][j][3] + bj[j].y);
            *(float2*)(out + o0) = v0;
            *(float2*)(out + o1) = v1;
        }
    }
}

// -----------------------------------------------------------------------------
extern "C" void kernel_launch(void* const* d_in, const int* in_sizes, int n_in,
                              void* d_out, int out_size) {
    const float*        x = (const float*)d_in[0];
    const float*        c = (const float*)d_in[1];
    const unsigned int* E = (const unsigned int*)d_in[2];
    const float*        W = (const float*)d_in[3];
    const float*        b = (const float*)d_in[4];
    float*            out = (float*)d_out;

    int nc = in_sizes[1];
    int M  = in_sizes[0] / D1;      // 8192

    float *U, *V;
    __nv_bfloat16 *Wh, *Wl, *Xh, *Xl;
    cudaGetSymbolAddress((void**)&U,  g_U);
    cudaGetSymbolAddress((void**)&V,  g_V);
    cudaGetSymbolAddress((void**)&Wh, g_Wh);
    cudaGetSymbolAddress((void**)&Wl, g_Wl);
    cudaGetSymbolAddress((void**)&Xh, g_Xh);
    cudaGetSymbolAddress((void**)&Xl, g_Xl);

    float scale = ALPHA / ((float)D1 * (float)D2);

    decode_E_kernel<<<1, 32>>>(E, nc);
    build_uv_kernel<<<dim3(D1, 2), 128>>>(c, nc, scale);

    sgemm_uv_kernel<<<dim3(D1 / 128, D2 / 128), 256>>>(
        V, UV_LD, U, UV_LD, Wh, Wl, D1, 2 * nc, W, D1);

    size_t n4 = (size_t)M * D1 / 4;
    split_kernel<<<(unsigned)((n4 + 255) / 256), 256>>>(x, Xh, Xl, n4);

    cudaFuncSetAttribute(gemm_mma_kernel,
                         cudaFuncAttributeMaxDynamicSharedMemorySize, SMEM_MAIN);
    gemm_mma_kernel<<<dim3(D2 / BN, M / BM), 256, SMEM_MAIN>>>(
        Xh, Xl, Wh, Wl, b, out);
}

// round 5
// speedup vs baseline: 4.3484x; 1.4977x over previous
#include <cuda_runtime.h>
#include <cuda_bf16.h>
#include <cuda_fp16.h>
#include <cstdint>

#define D1 4096
#define D2 4096
#define KTOT 4096
#define ALPHA 300.0f

// ---- main GEMM tiling ----
#define BM 256
#define BN 128
#define BK 32
#define STAGES 4
#define RSB 80                          // padded row stride bytes (40 fp16)
#define A_OFF 0
#define BH_OFF (BM * RSB)               // 20480
#define BL_OFF ((BM + BN) * RSB)        // 30720
#define STG_BYTES ((BM + 2 * BN) * RSB) // 40960
#define SMEM_MAIN (STAGES * STG_BYTES)  // 163840
#define NCH (KTOT / BK)                 // 128

// ---- wsplit GEMM ----
#define KUV 256
#define RS2 528                          // 256 bf16 = 512B + 16B pad
#define WS_SMEM (2 * 128 * RS2)          // 135168

// ---------------- device globals (scratch) -----------------------------------
__device__ int   g_rows[256];
__device__ int   g_cols[256];
__device__ __nv_bfloat16 g_Ub[D1 * KUV];
__device__ __nv_bfloat16 g_Vb[D2 * KUV];
__device__ __half g_Whh[(size_t)D2 * D1];
__device__ __half g_Whl[(size_t)D2 * D1];
__device__ __half g_X1[(size_t)8192 * D1];

// ---------------- PTX helpers (portable, sm_80-era) ---------------------------
__device__ __forceinline__ uint32_t smem_u32(const void* p) {
    uint32_t a;
    asm("{ .reg .u64 t; cvta.to.shared.u64 t, %1; cvt.u32.u64 %0, t; }" : "=r"(a) : "l"(p));
    return a;
}
__device__ __forceinline__ void cpa16(uint32_t d, const void* s) {
    asm volatile("cp.async.cg.shared.global [%0], [%1], 16;"
                 :: "r"(d), "l"(__cvta_generic_to_global(s)) : "memory");
}
__device__ __forceinline__ void ldsm4(uint32_t* r, uint32_t addr) {
    asm volatile("ldmatrix.sync.aligned.m8n8.x4.shared.b16 {%0,%1,%2,%3}, [%4];"
                 : "=r"(r[0]), "=r"(r[1]), "=r"(r[2]), "=r"(r[3]) : "r"(addr));
}
__device__ __forceinline__ void mma_f16(float* c, const uint32_t* a, const uint32_t* b) {
    asm volatile(
        "mma.sync.aligned.m16n8k16.row.col.f32.f16.f16.f32 "
        "{%0,%1,%2,%3}, {%4,%5,%6,%7}, {%8,%9}, {%0,%1,%2,%3};"
        : "+f"(c[0]), "+f"(c[1]), "+f"(c[2]), "+f"(c[3])
        : "r"(a[0]), "r"(a[1]), "r"(a[2]), "r"(a[3]), "r"(b[0]), "r"(b[1]));
}
__device__ __forceinline__ void mma_bf16(float* c, const uint32_t* a, const uint32_t* b) {
    asm volatile(
        "mma.sync.aligned.m16n8k16.row.col.f32.bf16.bf16.f32 "
        "{%0,%1,%2,%3}, {%4,%5,%6,%7}, {%8,%9}, {%0,%1,%2,%3};"
        : "+f"(c[0]), "+f"(c[1]), "+f"(c[2]), "+f"(c[3])
        : "r"(a[0]), "r"(a[1]), "r"(a[2]), "r"(a[3]), "r"(b[0]), "r"(b[1]));
}

// ---------------- decode E (int32 or int64 storage) ---------------------------
__global__ void decode_E_kernel(const unsigned int* __restrict__ ew, int nc) {
    if (threadIdx.x != 0) return;
    unsigned int oddor = 0;
    for (int i = 0; i < nc; ++i) oddor |= ew[2 * i + 1];
    bool is64 = (oddor == 0u);
    for (int j = 0; j < nc; ++j) {
        if (is64) { g_rows[j] = (int)ew[4 * j]; g_cols[j] = (int)ew[4 * (nc + j)]; }
        else      { g_rows[j] = (int)ew[j];     g_cols[j] = (int)ew[nc + j]; }
    }
}

// ---------------- build U, V (bf16, zero-padded to KUV cols) -------------------
__global__ void build_uv_kernel(const float* __restrict__ c, int nc, float scale) {
    int k = blockIdx.x, j = threadIdx.x;
    bool isV = (blockIdx.y != 0);
    __nv_bfloat16* dst = (isV ? g_Vb : g_Ub) + (size_t)k * KUV;
    if (j < nc) {
        int f = isV ? g_cols[j] : g_rows[j];
        int p = (f * k) & (D1 - 1);
        float ang = (float)p * (6.2831853071795864769f / (float)D1);
        float sn, cs;
        sincosf(ang, &sn, &cs);
        if (isV) {
            dst[2 * j]     = __float2bfloat16(cs);
            dst[2 * j + 1] = __float2bfloat16(sn);
        } else {
            float a = c[j] * scale;
            dst[2 * j]     = __float2bfloat16(a * cs);
            dst[2 * j + 1] = __float2bfloat16(-a * sn);
        }
    } else {
        dst[2 * j]     = __float2bfloat16(0.f);
        dst[2 * j + 1] = __float2bfloat16(0.f);
    }
}

// ---------------- wsplit: Wc[l,k] = sum_t V[l,t]U[k,t] + W[l,k] -> fp16 hi/lo --
// bf16 tensor-core GEMM, K=256, CTA 128x128, 8 warps (4x2), warp tile 32x64
__global__ void __launch_bounds__(256, 1)
wsplit_kernel(const float* __restrict__ W,
              __half* __restrict__ Whh, __half* __restrict__ Whl) {
    extern __shared__ __align__(128) char smem[];
    const uint32_t sb = smem_u32(smem);
    const uint32_t sbV = sb, sbU = sb + 128 * RS2;
    const int tid = threadIdx.x, lane = tid & 31, wid = tid >> 5;
    const int wm = wid & 3, wn = wid >> 2;
    const int l0 = blockIdx.y * 128, k0 = blockIdx.x * 128;

    // load V rows l0.. and U rows k0.. : 128 rows x 32 segs of 16B each matrix
#pragma unroll
    for (int it = 0; it < 16; ++it) {
        int idx = it * 256 + tid;
        int row = idx >> 5, seg = idx & 31;
        uint32_t so = (uint32_t)(row * RS2 + seg * 16);
        cpa16(sbV + so, g_Vb + (size_t)(l0 + row) * KUV + seg * 8);
        cpa16(sbU + so, g_Ub + (size_t)(k0 + row) * KUV + seg * 8);
    }
    asm volatile("cp.async.commit_group;" ::: "memory");
    asm volatile("cp.async.wait_group 0;" ::: "memory");
    __syncthreads();

    const int a_row = (lane & 7) + ((lane >> 3) & 1) * 8;
    const int a_col = ((lane >> 4) & 1) * 8;
    const uint32_t a_off = (uint32_t)((wm * 32 + a_row) * RS2 + a_col * 2);
    const int b_row = (lane & 7) + ((lane >> 4) & 1) * 8;
    const int b_col = ((lane >> 3) & 1) * 8;
    const uint32_t b_off = (uint32_t)((wn * 64 + b_row) * RS2 + b_col * 2);

    float acc[2][8][4];
#pragma unroll
    for (int i = 0; i < 2; ++i)
#pragma unroll
        for (int j = 0; j < 8; ++j)
#pragma unroll
            for (int q = 0; q < 4; ++q) acc[i][j][q] = 0.f;

#pragma unroll
    for (int ks = 0; ks < KUV / 16; ++ks) {
        uint32_t a[2][4], b[8][2];
#pragma unroll
        for (int i = 0; i < 2; ++i)
            ldsm4(a[i], sbV + a_off + i * (16 * RS2) + ks * 32);
#pragma unroll
        for (int j = 0; j < 4; ++j) {
            uint32_t t4[4];
            ldsm4(t4, sbU + b_off + j * (16 * RS2) + ks * 32);
            b[2*j][0] = t4[0]; b[2*j][1] = t4[1];
            b[2*j+1][0] = t4[2]; b[2*j+1][1] = t4[3];
        }
#pragma unroll
        for (int i = 0; i < 2; ++i)
#pragma unroll
            for (int j = 0; j < 8; ++j)
                mma_bf16(acc[i][j], a[i], b[j]);
    }

    // epilogue: add W (fp32), split to fp16 hi/lo
    const int crow = l0 + wm * 32 + (lane >> 2);
    const int ccol = k0 + wn * 64 + 2 * (lane & 3);
#pragma unroll
    for (int i = 0; i < 2; ++i) {
#pragma unroll
        for (int j = 0; j < 8; ++j) {
#pragma unroll
            for (int h = 0; h < 2; ++h) {        // h=0: rows, h=1: rows+8
                int r = crow + i * 16 + h * 8;
                size_t o = (size_t)r * D1 + ccol + j * 8;
                float2 w = *(const float2*)(W + o);
                float v0 = acc[i][j][2*h]   + w.x;
                float v1 = acc[i][j][2*h+1] + w.y;
                __half h0 = __float2half_rn(v0);
                __half h1 = __float2half_rn(v1);
                __half l0h = __float2half_rn(v0 - __half2float(h0));
                __half l1h = __float2half_rn(v1 - __half2float(h1));
                *(__half2*)(Whh + o) = __halves2half2(h0, h1);
                *(__half2*)(Whl + o) = __halves2half2(l0h, l1h);
            }
        }
    }
}

// ---------------- convert x -> fp16 -------------------------------------------
__global__ void xcvt_kernel(const float* __restrict__ s,
                            __half* __restrict__ d, size_t n4) {
    size_t i = blockIdx.x * (size_t)blockDim.x + threadIdx.x;
    if (i >= n4) return;
    float4 v = ((const float4*)s)[i];
    __half2 a = __halves2half2(__float2half_rn(v.x), __float2half_rn(v.y));
    __half2 b = __halves2half2(__float2half_rn(v.z), __float2half_rn(v.w));
    ((uint2*)d)[i] = make_uint2(*(uint32_t*)&a, *(uint32_t*)&b);
}

// ---------------- main GEMM: out = X1 (Whh+Whl)^T + b  (fp16x2, mma.sync) -----
// CTA 256x128x32, 4-stage cp.async, 8 warps in 4x2 -> warp tile 64x64
__global__ void __launch_bounds__(256, 1)
gemm_mma_kernel(const __half* __restrict__ X1,
                const __half* __restrict__ Wh,
                const __half* __restrict__ Wl,
                const float* __restrict__ bias,
                float* __restrict__ out) {
    extern __shared__ __align__(128) char smem[];
    const uint32_t sb = smem_u32(smem);
    const int tid  = threadIdx.x;
    const int lane = tid & 31;
    const int wid  = tid >> 5;
    const int wm   = wid & 3;
    const int wn   = wid >> 2;
    const int m0   = blockIdx.y * BM;
    const int n0   = blockIdx.x * BN;

    auto load_chunk = [&](int stg, int chunk) {
        const uint32_t base = sb + stg * STG_BYTES;
        const int kc = chunk * BK;
#pragma unroll
        for (int it = 0; it < 4; ++it) {         // A: 256 rows x 4 segs
            int idx = it * 256 + tid;
            int row = idx >> 2, seg = idx & 3;
            uint32_t so = (uint32_t)(row * RSB + seg * 16);
            cpa16(base + A_OFF + so, X1 + (size_t)(m0 + row) * KTOT + kc + seg * 8);
        }
#pragma unroll
        for (int it = 0; it < 2; ++it) {         // B: 128 rows x 4 segs, hi+lo
            int idx = it * 256 + tid;
            int row = idx >> 2, seg = idx & 3;
            uint32_t so = (uint32_t)(row * RSB + seg * 16);
            size_t g = (size_t)(n0 + row) * KTOT + kc + seg * 8;
            cpa16(base + BH_OFF + so, Wh + g);
            cpa16(base + BL_OFF + so, Wl + g);
        }
    };

    const int a_row = (lane & 7) + ((lane >> 3) & 1) * 8;
    const int a_col = ((lane >> 4) & 1) * 8;
    const uint32_t a_off = (uint32_t)((wm * 64 + a_row) * RSB + a_col * 2);
    const int b_row = (lane & 7) + ((lane >> 4) & 1) * 8;
    const int b_col = ((lane >> 3) & 1) * 8;
    const uint32_t b_off = (uint32_t)((wn * 64 + b_row) * RSB + b_col * 2);

    float acc[4][8][4];
#pragma unroll
    for (int i = 0; i < 4; ++i)
#pragma unroll
        for (int j = 0; j < 8; ++j)
#pragma unroll
            for (int q = 0; q < 4; ++q) acc[i][j][q] = 0.f;

#pragma unroll
    for (int s = 0; s < STAGES - 1; ++s) {
        load_chunk(s, s);
        asm volatile("cp.async.commit_group;" ::: "memory");
    }

    for (int it = 0; it < NCH; ++it) {
        asm volatile("cp.async.wait_group %0;" :: "n"(STAGES - 2) : "memory");
        __syncthreads();

        if (it + STAGES - 1 < NCH) load_chunk((it + STAGES - 1) % STAGES, it + STAGES - 1);
        asm volatile("cp.async.commit_group;" ::: "memory");

        const uint32_t st = sb + (it % STAGES) * STG_BYTES;
#pragma unroll
        for (int kk = 0; kk < 2; ++kk) {
            uint32_t a[4][4], bh[8][2], bl[8][2];
#pragma unroll
            for (int i = 0; i < 4; ++i)
                ldsm4(a[i], st + A_OFF + a_off + i * (16 * RSB) + kk * 32);
#pragma unroll
            for (int j = 0; j < 4; ++j) {
                uint32_t t4[4];
                ldsm4(t4, st + BH_OFF + b_off + j * (16 * RSB) + kk * 32);
                bh[2*j][0] = t4[0]; bh[2*j][1] = t4[1];
                bh[2*j+1][0] = t4[2]; bh[2*j+1][1] = t4[3];
                ldsm4(t4, st + BL_OFF + b_off + j * (16 * RSB) + kk * 32);
                bl[2*j][0] = t4[0]; bl[2*j][1] = t4[1];
                bl[2*j+1][0] = t4[2]; bl[2*j+1][1] = t4[3];
            }
#pragma unroll
            for (int i = 0; i < 4; ++i)
#pragma unroll
                for (int j = 0; j < 8; ++j) {
                    mma_f16(acc[i][j], a[i], bh[j]);
                    mma_f16(acc[i][j], a[i], bl[j]);
                }
        }
    }

    // epilogue
    const int col_base = n0 + wn * 64 + 2 * (lane & 3);
    float2 bj[8];
#pragma unroll
    for (int j = 0; j < 8; ++j) {
        bj[j].x = __ldg(bias + col_base + j * 8);
        bj[j].y = __ldg(bias + col_base + j * 8 + 1);
    }
    const int row_base = m0 + wm * 64 + (lane >> 2);
#pragma unroll
    for (int i = 0; i < 4; ++i) {
#pragma unroll
        for (int j = 0; j < 8; ++j) {
            size_t o0 = (size_t)(row_base + i * 16) * D2 + col_base + j * 8;
            size_t o1 = o0 + 8 * D2;
            *(float2*)(out + o0) = make_float2(acc[i][j][0] + bj[j].x, acc[i][j][1] + bj[j].y);
            *(float2*)(out + o1) = make_float2(acc[i][j][2] + bj[j].x, acc[i][j][3] + bj[j].y);
        }
    }
}

// -----------------------------------------------------------------------------
extern "C" void kernel_launch(void* const* d_in, const int* in_sizes, int n_in,
                              void* d_out, int out_size) {
    const float*        x = (const float*)d_in[0];
    const float*        c = (const float*)d_in[1];
    const unsigned int* E = (const unsigned int*)d_in[2];
    const float*        W = (const float*)d_in[3];
    const float*        b = (const float*)d_in[4];
    float*            out = (float*)d_out;

    int nc = in_sizes[1];
    int M  = in_sizes[0] / D1;      // 8192

    __half *Whh, *Whl, *X1;
    cudaGetSymbolAddress((void**)&Whh, g_Whh);
    cudaGetSymbolAddress((void**)&Whl, g_Whl);
    cudaGetSymbolAddress((void**)&X1,  g_X1);

    float scale = ALPHA / ((float)D1 * (float)D2);

    decode_E_kernel<<<1, 32>>>(E, nc);
    build_uv_kernel<<<dim3(D1, 2), 128>>>(c, nc, scale);

    cudaFuncSetAttribute(wsplit_kernel,
                         cudaFuncAttributeMaxDynamicSharedMemorySize, WS_SMEM);
    wsplit_kernel<<<dim3(D1 / 128, D2 / 128), 256, WS_SMEM>>>(W, Whh, Whl);

    size_t n4 = (size_t)M * D1 / 4;
    xcvt_kernel<<<(unsigned)((n4 + 255) / 256), 256>>>(x, X1, n4);

    cudaFuncSetAttribute(gemm_mma_kernel,
                         cudaFuncAttributeMaxDynamicSharedMemorySize, SMEM_MAIN);
    gemm_mma_kernel<<<dim3(D2 / BN, M / BM), 256, SMEM_MAIN>>>(
        X1, Whh, Whl, b, out);
}

// round 6
// speedup vs baseline: 6.8988x; 1.5865x over previous
#include <cuda_runtime.h>
#include <cuda_bf16.h>
#include <cuda_fp16.h>
#include <cstdint>

#define D1 4096
#define D2 4096
#define KTOT 4096
#define ALPHA 300.0f

// ---- main GEMM tiling ----
#define BM 256
#define BN 128
#define BK 32
#define STAGES 4
#define RSB 80                          // padded row stride bytes (40 fp16)
#define A_OFF 0
#define B_OFF (BM * RSB)                // 20480
#define STG_BYTES ((BM + BN) * RSB)     // 30720
#define SMEM_MAIN (STAGES * STG_BYTES)  // 122880
#define NCH (KTOT / BK)                 // 128

// ---- wsplit GEMM ----
#define KUV 256
#define RS2 528                          // 256 bf16 = 512B + 16B pad
#define WS_SMEM (2 * 128 * RS2)          // 135168

// ---------------- device globals (scratch) -----------------------------------
__device__ int   g_rows[256];
__device__ int   g_cols[256];
__device__ __nv_bfloat16 g_Ub[D1 * KUV];
__device__ __nv_bfloat16 g_Vb[D2 * KUV];
__device__ __half g_Wc[(size_t)D2 * D1];
__device__ __half g_X1[(size_t)8192 * D1];

// ---------------- PTX helpers (portable, sm_80-era) ---------------------------
__device__ __forceinline__ uint32_t smem_u32(const void* p) {
    uint32_t a;
    asm("{ .reg .u64 t; cvta.to.shared.u64 t, %1; cvt.u32.u64 %0, t; }" : "=r"(a) : "l"(p));
    return a;
}
__device__ __forceinline__ void cpa16(uint32_t d, const void* s) {
    asm volatile("cp.async.cg.shared.global [%0], [%1], 16;"
                 :: "r"(d), "l"(__cvta_generic_to_global(s)) : "memory");
}
__device__ __forceinline__ void ldsm4(uint32_t* r, uint32_t addr) {
    asm volatile("ldmatrix.sync.aligned.m8n8.x4.shared.b16 {%0,%1,%2,%3}, [%4];"
                 : "=r"(r[0]), "=r"(r[1]), "=r"(r[2]), "=r"(r[3]) : "r"(addr));
}
__device__ __forceinline__ void mma_f16(float* c, const uint32_t* a, const uint32_t* b) {
    asm volatile(
        "mma.sync.aligned.m16n8k16.row.col.f32.f16.f16.f32 "
        "{%0,%1,%2,%3}, {%4,%5,%6,%7}, {%8,%9}, {%0,%1,%2,%3};"
        : "+f"(c[0]), "+f"(c[1]), "+f"(c[2]), "+f"(c[3])
        : "r"(a[0]), "r"(a[1]), "r"(a[2]), "r"(a[3]), "r"(b[0]), "r"(b[1]));
}
__device__ __forceinline__ void mma_bf16(float* c, const uint32_t* a, const uint32_t* b) {
    asm volatile(
        "mma.sync.aligned.m16n8k16.row.col.f32.bf16.bf16.f32 "
        "{%0,%1,%2,%3}, {%4,%5,%6,%7}, {%8,%9}, {%0,%1,%2,%3};"
        : "+f"(c[0]), "+f"(c[1]), "+f"(c[2]), "+f"(c[3])
        : "r"(a[0]), "r"(a[1]), "r"(a[2]), "r"(a[3]), "r"(b[0]), "r"(b[1]));
}

// ---------------- decode E (int32 or int64 storage) ---------------------------
__global__ void decode_E_kernel(const unsigned int* __restrict__ ew, int nc) {
    if (threadIdx.x != 0) return;
    unsigned int oddor = 0;
    for (int i = 0; i < nc; ++i) oddor |= ew[2 * i + 1];
    bool is64 = (oddor == 0u);
    for (int j = 0; j < nc; ++j) {
        if (is64) { g_rows[j] = (int)ew[4 * j]; g_cols[j] = (int)ew[4 * (nc + j)]; }
        else      { g_rows[j] = (int)ew[j];     g_cols[j] = (int)ew[nc + j]; }
    }
}

// ---------------- build U, V (bf16, zero-padded to KUV cols) -------------------
__global__ void build_uv_kernel(const float* __restrict__ c, int nc, float scale) {
    int k = blockIdx.x, j = threadIdx.x;
    bool isV = (blockIdx.y != 0);
    __nv_bfloat16* dst = (isV ? g_Vb : g_Ub) + (size_t)k * KUV;
    if (j < nc) {
        int f = isV ? g_cols[j] : g_rows[j];
        int p = (f * k) & (D1 - 1);
        float ang = (float)p * (6.2831853071795864769f / (float)D1);
        float sn, cs;
        sincosf(ang, &sn, &cs);
        if (isV) {
            dst[2 * j]     = __float2bfloat16(cs);
            dst[2 * j + 1] = __float2bfloat16(sn);
        } else {
            float a = c[j] * scale;
            dst[2 * j]     = __float2bfloat16(a * cs);
            dst[2 * j + 1] = __float2bfloat16(-a * sn);
        }
    } else {
        dst[2 * j]     = __float2bfloat16(0.f);
        dst[2 * j + 1] = __float2bfloat16(0.f);
    }
}

// ---------------- wsplit: Wc[l,k] = sum_t V[l,t]U[k,t] + W[l,k] -> fp16 --------
// bf16 tensor-core GEMM, K=256, CTA 128x128, 8 warps (4x2), warp tile 32x64
__global__ void __launch_bounds__(256, 1)
wsplit_kernel(const float* __restrict__ W, __half* __restrict__ Wc) {
    extern __shared__ __align__(128) char smem[];
    const uint32_t sb = smem_u32(smem);
    const uint32_t sbV = sb, sbU = sb + 128 * RS2;
    const int tid = threadIdx.x, lane = tid & 31, wid = tid >> 5;
    const int wm = wid & 3, wn = wid >> 2;
    const int l0 = blockIdx.y * 128, k0 = blockIdx.x * 128;

#pragma unroll
    for (int it = 0; it < 16; ++it) {
        int idx = it * 256 + tid;
        int row = idx >> 5, seg = idx & 31;
        uint32_t so = (uint32_t)(row * RS2 + seg * 16);
        cpa16(sbV + so, g_Vb + (size_t)(l0 + row) * KUV + seg * 8);
        cpa16(sbU + so, g_Ub + (size_t)(k0 + row) * KUV + seg * 8);
    }
    asm volatile("cp.async.commit_group;" ::: "memory");
    asm volatile("cp.async.wait_group 0;" ::: "memory");
    __syncthreads();

    const int a_row = (lane & 7) + ((lane >> 3) & 1) * 8;
    const int a_col = ((lane >> 4) & 1) * 8;
    const uint32_t a_off = (uint32_t)((wm * 32 + a_row) * RS2 + a_col * 2);
    const int b_row = (lane & 7) + ((lane >> 4) & 1) * 8;
    const int b_col = ((lane >> 3) & 1) * 8;
    const uint32_t b_off = (uint32_t)((wn * 64 + b_row) * RS2 + b_col * 2);

    float acc[2][8][4];
#pragma unroll
    for (int i = 0; i < 2; ++i)
#pragma unroll
        for (int j = 0; j < 8; ++j)
#pragma unroll
            for (int q = 0; q < 4; ++q) acc[i][j][q] = 0.f;

#pragma unroll
    for (int ks = 0; ks < KUV / 16; ++ks) {
        uint32_t a[2][4], b[8][2];
#pragma unroll
        for (int i = 0; i < 2; ++i)
            ldsm4(a[i], sbV + a_off + i * (16 * RS2) + ks * 32);
#pragma unroll
        for (int j = 0; j < 4; ++j) {
            uint32_t t4[4];
            ldsm4(t4, sbU + b_off + j * (16 * RS2) + ks * 32);
            b[2*j][0] = t4[0]; b[2*j][1] = t4[1];
            b[2*j+1][0] = t4[2]; b[2*j+1][1] = t4[3];
        }
#pragma unroll
        for (int i = 0; i < 2; ++i)
#pragma unroll
            for (int j = 0; j < 8; ++j)
                mma_bf16(acc[i][j], a[i], b[j]);
    }

    const int crow = l0 + wm * 32 + (lane >> 2);
    const int ccol = k0 + wn * 64 + 2 * (lane & 3);
#pragma unroll
    for (int i = 0; i < 2; ++i) {
#pragma unroll
        for (int j = 0; j < 8; ++j) {
#pragma unroll
            for (int h = 0; h < 2; ++h) {
                int r = crow + i * 16 + h * 8;
                size_t o = (size_t)r * D1 + ccol + j * 8;
                float2 w = *(const float2*)(W + o);
                *(__half2*)(Wc + o) = __halves2half2(
                    __float2half_rn(acc[i][j][2*h]   + w.x),
                    __float2half_rn(acc[i][j][2*h+1] + w.y));
            }
        }
    }
}

// ---------------- convert x -> fp16 -------------------------------------------
__global__ void xcvt_kernel(const float* __restrict__ s,
                            __half* __restrict__ d, size_t n4) {
    size_t i = blockIdx.x * (size_t)blockDim.x + threadIdx.x;
    if (i >= n4) return;
    float4 v = ((const float4*)s)[i];
    __half2 a = __halves2half2(__float2half_rn(v.x), __float2half_rn(v.y));
    __half2 b = __halves2half2(__float2half_rn(v.z), __float2half_rn(v.w));
    ((uint2*)d)[i] = make_uint2(*(uint32_t*)&a, *(uint32_t*)&b);
}

// ---------------- main GEMM: out = X1 Wc^T + b  (fp16, mma.sync) --------------
// CTA 256x128x32, 4-stage cp.async, 8 warps in 4x2 -> warp tile 64x64
__global__ void __launch_bounds__(256, 1)
gemm_mma_kernel(const __half* __restrict__ X1,
                const __half* __restrict__ Wc,
                const float* __restrict__ bias,
                float* __restrict__ out) {
    extern __shared__ __align__(128) char smem[];
    const uint32_t sb = smem_u32(smem);
    const int tid  = threadIdx.x;
    const int lane = tid & 31;
    const int wid  = tid >> 5;
    const int wm   = wid & 3;
    const int wn   = wid >> 2;
    const int m0   = blockIdx.y * BM;
    const int n0   = blockIdx.x * BN;

    auto load_chunk = [&](int stg, int chunk) {
        const uint32_t base = sb + stg * STG_BYTES;
        const int kc = chunk * BK;
#pragma unroll
        for (int it = 0; it < 4; ++it) {         // A: 256 rows x 4 segs
            int idx = it * 256 + tid;
            int row = idx >> 2, seg = idx & 3;
            uint32_t so = (uint32_t)(row * RSB + seg * 16);
            cpa16(base + A_OFF + so, X1 + (size_t)(m0 + row) * KTOT + kc + seg * 8);
        }
#pragma unroll
        for (int it = 0; it < 2; ++it) {         // B: 128 rows x 4 segs
            int idx = it * 256 + tid;
            int row = idx >> 2, seg = idx & 3;
            uint32_t so = (uint32_t)(row * RSB + seg * 16);
            cpa16(base + B_OFF + so, Wc + (size_t)(n0 + row) * KTOT + kc + seg * 8);
        }
    };

    const int a_row = (lane & 7) + ((lane >> 3) & 1) * 8;
    const int a_col = ((lane >> 4) & 1) * 8;
    const uint32_t a_off = (uint32_t)((wm * 64 + a_row) * RSB + a_col * 2);
    const int b_row = (lane & 7) + ((lane >> 4) & 1) * 8;
    const int b_col = ((lane >> 3) & 1) * 8;
    const uint32_t b_off = (uint32_t)((wn * 64 + b_row) * RSB + b_col * 2);

    float acc[4][8][4];
#pragma unroll
    for (int i = 0; i < 4; ++i)
#pragma unroll
        for (int j = 0; j < 8; ++j)
#pragma unroll
            for (int q = 0; q < 4; ++q) acc[i][j][q] = 0.f;

#pragma unroll
    for (int s = 0; s < STAGES - 1; ++s) {
        load_chunk(s, s);
        asm volatile("cp.async.commit_group;" ::: "memory");
    }

    for (int it = 0; it < NCH; ++it) {
        asm volatile("cp.async.wait_group %0;" :: "n"(STAGES - 2) : "memory");
        __syncthreads();

        if (it + STAGES - 1 < NCH) load_chunk((it + STAGES - 1) % STAGES, it + STAGES - 1);
        asm volatile("cp.async.commit_group;" ::: "memory");

        const uint32_t st = sb + (it % STAGES) * STG_BYTES;
#pragma unroll
        for (int kk = 0; kk < 2; ++kk) {
            uint32_t a[4][4], b[8][2];
#pragma unroll
            for (int i = 0; i < 4; ++i)
                ldsm4(a[i], st + A_OFF + a_off + i * (16 * RSB) + kk * 32);
#pragma unroll
            for (int j = 0; j < 4; ++j) {
                uint32_t t4[4];
                ldsm4(t4, st + B_OFF + b_off + j * (16 * RSB) + kk * 32);
                b[2*j][0] = t4[0]; b[2*j][1] = t4[1];
                b[2*j+1][0] = t4[2]; b[2*j+1][1] = t4[3];
            }
#pragma unroll
            for (int i = 0; i < 4; ++i)
#pragma unroll
                for (int j = 0; j < 8; ++j)
                    mma_f16(acc[i][j], a[i], b[j]);
        }
    }

    // epilogue
    const int col_base = n0 + wn * 64 + 2 * (lane & 3);
    float2 bj[8];
#pragma unroll
    for (int j = 0; j < 8; ++j) {
        bj[j].x = __ldg(bias + col_base + j * 8);
        bj[j].y = __ldg(bias + col_base + j * 8 + 1);
    }
    const int row_base = m0 + wm * 64 + (lane >> 2);
#pragma unroll
    for (int i = 0; i < 4; ++i) {
#pragma unroll
        for (int j = 0; j < 8; ++j) {
            size_t o0 = (size_t)(row_base + i * 16) * D2 + col_base + j * 8;
            size_t o1 = o0 + 8 * D2;
            *(float2*)(out + o0) = make_float2(acc[i][j][0] + bj[j].x, acc[i][j][1] + bj[j].y);
            *(float2*)(out + o1) = make_float2(acc[i][j][2] + bj[j].x, acc[i][j][3] + bj[j].y);
        }
    }
}

// -----------------------------------------------------------------------------
extern "C" void kernel_launch(void* const* d_in, const int* in_sizes, int n_in,
                              void* d_out, int out_size) {
    const float*        x = (const float*)d_in[0];
    const float*        c = (const float*)d_in[1];
    const unsigned int* E = (const unsigned int*)d_in[2];
    const float*        W = (const float*)d_in[3];
    const float*        b = (const float*)d_in[4];
    float*            out = (float*)d_out;

    int nc = in_sizes[1];
    int M  = in_sizes[0] / D1;      // 8192

    __half *Wc, *X1;
    cudaGetSymbolAddress((void**)&Wc, g_Wc);
    cudaGetSymbolAddress((void**)&X1, g_X1);

    float scale = ALPHA / ((float)D1 * (float)D2);

    decode_E_kernel<<<1, 32>>>(E, nc);
    build_uv_kernel<<<dim3(D1, 2), 128>>>(c, nc, scale);

    cudaFuncSetAttribute(wsplit_kernel,
                         cudaFuncAttributeMaxDynamicSharedMemorySize, WS_SMEM);
    wsplit_kernel<<<dim3(D1 / 128, D2 / 128), 256, WS_SMEM>>>(W, Wc);

    size_t n4 = (size_t)M * D1 / 4;
    xcvt_kernel<<<(unsigned)((n4 + 255) / 256), 256>>>(x, X1, n4);

    cudaFuncSetAttribute(gemm_mma_kernel,
                         cudaFuncAttributeMaxDynamicSharedMemorySize, SMEM_MAIN);
    gemm_mma_kernel<<<dim3(D2 / BN, M / BM), 256, SMEM_MAIN>>>(
        X1, Wc, b, out);
}

// round 8
// speedup vs baseline: 7.8541x; 1.1385x over previous
#include <cuda_runtime.h>
#include <cuda_bf16.h>
#include <cuda_fp16.h>
#include <cstdint>

#define D1 4096
#define D2 4096
#define KTOT 4096
#define ALPHA 300.0f

// ---- main GEMM tiling ----
#define BM 256
#define BN 128
#define BK 64
#define STAGES 3
#define RSB 144                          // 128B row + 16B pad (16B-aligned!)
#define A_OFF 0
#define B_OFF (BM * RSB)                 // 36864
#define STG_BYTES ((BM + BN) * RSB)      // 55296
#define SMEM_MAIN (STAGES * STG_BYTES)   // 165888
#define NCH (KTOT / BK)                  // 64

// ---- wsplit GEMM ----
#define KUV 256
#define RS2 528
#define WS_SMEM (2 * 128 * RS2)

// ---------------- device globals (scratch) -----------------------------------
__device__ int   g_rows[256];
__device__ int   g_cols[256];
__device__ __nv_bfloat16 g_Ub[D1 * KUV];
__device__ __nv_bfloat16 g_Vb[D2 * KUV];
__device__ __half g_Wc[(size_t)D2 * D1];
__device__ __half g_X1[(size_t)8192 * D1];

// ---------------- PTX helpers (portable, sm_80-era) ---------------------------
__device__ __forceinline__ uint32_t smem_u32(const void* p) {
    uint32_t a;
    asm("{ .reg .u64 t; cvta.to.shared.u64 t, %1; cvt.u32.u64 %0, t; }" : "=r"(a) : "l"(p));
    return a;
}
__device__ __forceinline__ void cpa16(uint32_t d, const void* s) {
    asm volatile("cp.async.cg.shared.global [%0], [%1], 16;"
                 :: "r"(d), "l"(__cvta_generic_to_global(s)) : "memory");
}
__device__ __forceinline__ void ldsm4(uint32_t* r, uint32_t addr) {
    asm volatile("ldmatrix.sync.aligned.m8n8.x4.shared.b16 {%0,%1,%2,%3}, [%4];"
                 : "=r"(r[0]), "=r"(r[1]), "=r"(r[2]), "=r"(r[3]) : "r"(addr));
}
__device__ __forceinline__ void mma_f16(float* c, const uint32_t* a, const uint32_t* b) {
    asm volatile(
        "mma.sync.aligned.m16n8k16.row.col.f32.f16.f16.f32 "
        "{%0,%1,%2,%3}, {%4,%5,%6,%7}, {%8,%9}, {%0,%1,%2,%3};"
        : "+f"(c[0]), "+f"(c[1]), "+f"(c[2]), "+f"(c[3])
        : "r"(a[0]), "r"(a[1]), "r"(a[2]), "r"(a[3]), "r"(b[0]), "r"(b[1]));
}
__device__ __forceinline__ void mma_bf16(float* c, const uint32_t* a, const uint32_t* b) {
    asm volatile(
        "mma.sync.aligned.m16n8k16.row.col.f32.bf16.bf16.f32 "
        "{%0,%1,%2,%3}, {%4,%5,%6,%7}, {%8,%9}, {%0,%1,%2,%3};"
        : "+f"(c[0]), "+f"(c[1]), "+f"(c[2]), "+f"(c[3])
        : "r"(a[0]), "r"(a[1]), "r"(a[2]), "r"(a[3]), "r"(b[0]), "r"(b[1]));
}

// ---------------- decode E (int32 or int64 storage) ---------------------------
__global__ void decode_E_kernel(const unsigned int* __restrict__ ew, int nc) {
    if (threadIdx.x != 0) return;
    unsigned int oddor = 0;
    for (int i = 0; i < nc; ++i) oddor |= ew[2 * i + 1];
    bool is64 = (oddor == 0u);
    for (int j = 0; j < nc; ++j) {
        if (is64) { g_rows[j] = (int)ew[4 * j]; g_cols[j] = (int)ew[4 * (nc + j)]; }
        else      { g_rows[j] = (int)ew[j];     g_cols[j] = (int)ew[nc + j]; }
    }
}

// ---------------- build U, V (bf16, zero-padded to KUV cols) -------------------
__global__ void build_uv_kernel(const float* __restrict__ c, int nc, float scale) {
    int k = blockIdx.x, j = threadIdx.x;
    bool isV = (blockIdx.y != 0);
    __nv_bfloat16* dst = (isV ? g_Vb : g_Ub) + (size_t)k * KUV;
    if (j < nc) {
        int f = isV ? g_cols[j] : g_rows[j];
        int p = (f * k) & (D1 - 1);
        float ang = (float)p * (6.2831853071795864769f / (float)D1);
        float sn, cs;
        sincosf(ang, &sn, &cs);
        if (isV) {
            dst[2 * j]     = __float2bfloat16(cs);
            dst[2 * j + 1] = __float2bfloat16(sn);
        } else {
            float a = c[j] * scale;
            dst[2 * j]     = __float2bfloat16(a * cs);
            dst[2 * j + 1] = __float2bfloat16(-a * sn);
        }
    } else {
        dst[2 * j]     = __float2bfloat16(0.f);
        dst[2 * j + 1] = __float2bfloat16(0.f);
    }
}

// ---------------- wsplit: Wc[l,k] = sum_t V[l,t]U[k,t] + W[l,k] -> fp16 --------
__global__ void __launch_bounds__(256, 1)
wsplit_kernel(const float* __restrict__ W, __half* __restrict__ Wc) {
    extern __shared__ __align__(128) char smem[];
    const uint32_t sb = smem_u32(smem);
    const uint32_t sbV = sb, sbU = sb + 128 * RS2;
    const int tid = threadIdx.x, lane = tid & 31, wid = tid >> 5;
    const int wm = wid & 3, wn = wid >> 2;
    const int l0 = blockIdx.y * 128, k0 = blockIdx.x * 128;

#pragma unroll
    for (int it = 0; it < 16; ++it) {
        int idx = it * 256 + tid;
        int row = idx >> 5, seg = idx & 31;
        uint32_t so = (uint32_t)(row * RS2 + seg * 16);
        cpa16(sbV + so, g_Vb + (size_t)(l0 + row) * KUV + seg * 8);
        cpa16(sbU + so, g_Ub + (size_t)(k0 + row) * KUV + seg * 8);
    }
    asm volatile("cp.async.commit_group;" ::: "memory");
    asm volatile("cp.async.wait_group 0;" ::: "memory");
    __syncthreads();

    const int a_row = (lane & 7) + ((lane >> 3) & 1) * 8;
    const int a_col = ((lane >> 4) & 1) * 8;
    const uint32_t a_off = (uint32_t)((wm * 32 + a_row) * RS2 + a_col * 2);
    const int b_row = (lane & 7) + ((lane >> 4) & 1) * 8;
    const int b_col = ((lane >> 3) & 1) * 8;
    const uint32_t b_off = (uint32_t)((wn * 64 + b_row) * RS2 + b_col * 2);

    float acc[2][8][4];
#pragma unroll
    for (int i = 0; i < 2; ++i)
#pragma unroll
        for (int j = 0; j < 8; ++j)
#pragma unroll
            for (int q = 0; q < 4; ++q) acc[i][j][q] = 0.f;

#pragma unroll
    for (int ks = 0; ks < KUV / 16; ++ks) {
        uint32_t a[2][4], b[8][2];
#pragma unroll
        for (int i = 0; i < 2; ++i)
            ldsm4(a[i], sbV + a_off + i * (16 * RS2) + ks * 32);
#pragma unroll
        for (int j = 0; j < 4; ++j) {
            uint32_t t4[4];
            ldsm4(t4, sbU + b_off + j * (16 * RS2) + ks * 32);
            b[2*j][0] = t4[0]; b[2*j][1] = t4[1];
            b[2*j+1][0] = t4[2]; b[2*j+1][1] = t4[3];
        }
#pragma unroll
        for (int i = 0; i < 2; ++i)
#pragma unroll
            for (int j = 0; j < 8; ++j)
                mma_bf16(acc[i][j], a[i], b[j]);
    }

    const int crow = l0 + wm * 32 + (lane >> 2);
    const int ccol = k0 + wn * 64 + 2 * (lane & 3);
#pragma unroll
    for (int i = 0; i < 2; ++i) {
#pragma unroll
        for (int j = 0; j < 8; ++j) {
#pragma unroll
            for (int h = 0; h < 2; ++h) {
                int r = crow + i * 16 + h * 8;
                size_t o = (size_t)r * D1 + ccol + j * 8;
                float2 w = *(const float2*)(W + o);
                *(__half2*)(Wc + o) = __halves2half2(
                    __float2half_rn(acc[i][j][2*h]   + w.x),
                    __float2half_rn(acc[i][j][2*h+1] + w.y));
            }
        }
    }
}

// ---------------- convert x -> fp16 -------------------------------------------
__global__ void xcvt_kernel(const float* __restrict__ s,
                            __half* __restrict__ d, size_t n4) {
    size_t i = blockIdx.x * (size_t)blockDim.x + threadIdx.x;
    if (i >= n4) return;
    float4 v = ((const float4*)s)[i];
    __half2 a = __halves2half2(__float2half_rn(v.x), __float2half_rn(v.y));
    __half2 b = __halves2half2(__float2half_rn(v.z), __float2half_rn(v.w));
    ((uint2*)d)[i] = make_uint2(*(uint32_t*)&a, *(uint32_t*)&b);
}

// ---------------- main GEMM: out = X1 Wc^T + b  (fp16, mma.sync) --------------
// CTA 256x128x64, 3-stage cp.async, 8 warps (4x2), warp tile 64x64,
// fragment double-buffered across the 4 k16 steps of each chunk.
__global__ void __launch_bounds__(256, 1)
gemm_mma_kernel(const __half* __restrict__ X1,
                const __half* __restrict__ Wc,
                const float* __restrict__ bias,
                float* __restrict__ out) {
    extern __shared__ __align__(128) char smem[];
    const uint32_t sb = smem_u32(smem);
    const int tid  = threadIdx.x;
    const int lane = tid & 31;
    const int wid  = tid >> 5;
    const int wm   = wid & 3;
    const int wn   = wid >> 2;
    const int m0   = blockIdx.y * BM;
    const int n0   = blockIdx.x * BN;

    auto load_chunk = [&](int stg, int chunk) {
        const uint32_t base = sb + stg * STG_BYTES;
        const int kc = chunk * BK;
#pragma unroll
        for (int it = 0; it < 8; ++it) {         // A: 256 rows x 8 segs of 16B
            int idx = it * 256 + tid;
            int row = idx >> 3, seg = idx & 7;
            uint32_t so = (uint32_t)(row * RSB + seg * 16);
            cpa16(base + A_OFF + so, X1 + (size_t)(m0 + row) * KTOT + kc + seg * 8);
        }
#pragma unroll
        for (int it = 0; it < 4; ++it) {         // B: 128 rows x 8 segs
            int idx = it * 256 + tid;
            int row = idx >> 3, seg = idx & 7;
            uint32_t so = (uint32_t)(row * RSB + seg * 16);
            cpa16(base + B_OFF + so, Wc + (size_t)(n0 + row) * KTOT + kc + seg * 8);
        }
    };

    const int a_row = (lane & 7) + ((lane >> 3) & 1) * 8;
    const int a_col = ((lane >> 4) & 1) * 8;
    const uint32_t a_off = (uint32_t)((wm * 64 + a_row) * RSB + a_col * 2);
    const int b_row = (lane & 7) + ((lane >> 4) & 1) * 8;
    const int b_col = ((lane >> 3) & 1) * 8;
    const uint32_t b_off = (uint32_t)((wn * 64 + b_row) * RSB + b_col * 2);

    uint32_t af[2][4][4], bf[2][8][2];
    auto ldfrag = [&](int buf, uint32_t st, int kk) {
#pragma unroll
        for (int i = 0; i < 4; ++i)
            ldsm4(af[buf][i], st + A_OFF + a_off + i * (16 * RSB) + kk * 32);
#pragma unroll
        for (int j = 0; j < 4; ++j) {
            uint32_t t4[4];
            ldsm4(t4, st + B_OFF + b_off + j * (16 * RSB) + kk * 32);
            bf[buf][2*j][0] = t4[0]; bf[buf][2*j][1] = t4[1];
            bf[buf][2*j+1][0] = t4[2]; bf[buf][2*j+1][1] = t4[3];
        }
    };

    float acc[4][8][4];
#pragma unroll
    for (int i = 0; i < 4; ++i)
#pragma unroll
        for (int j = 0; j < 8; ++j)
#pragma unroll
            for (int q = 0; q < 4; ++q) acc[i][j][q] = 0.f;

#pragma unroll
    for (int s = 0; s < STAGES - 1; ++s) {
        load_chunk(s, s);
        asm volatile("cp.async.commit_group;" ::: "memory");
    }

    for (int it = 0; it < NCH; ++it) {
        asm volatile("cp.async.wait_group %0;" :: "n"(STAGES - 2) : "memory");
        __syncthreads();

        if (it + STAGES - 1 < NCH) load_chunk((it + STAGES - 1) % STAGES, it + STAGES - 1);
        asm volatile("cp.async.commit_group;" ::: "memory");

        const uint32_t st = sb + (it % STAGES) * STG_BYTES;
        ldfrag(0, st, 0);
#pragma unroll
        for (int kk = 0; kk < 4; ++kk) {
            const int cur = kk & 1;
            if (kk < 3) ldfrag(cur ^ 1, st, kk + 1);
#pragma unroll
            for (int i = 0; i < 4; ++i)
#pragma unroll
                for (int j = 0; j < 8; ++j)
                    mma_f16(acc[i][j], af[cur][i], bf[cur][j]);
        }
    }

    // epilogue
    const int col_base = n0 + wn * 64 + 2 * (lane & 3);
    float2 bj[8];
#pragma unroll
    for (int j = 0; j < 8; ++j) {
        bj[j].x = __ldg(bias + col_base + j * 8);
        bj[j].y = __ldg(bias + col_base + j * 8 + 1);
    }
    const int row_base = m0 + wm * 64 + (lane >> 2);
#pragma unroll
    for (int i = 0; i < 4; ++i) {
#pragma unroll
        for (int j = 0; j < 8; ++j) {
            size_t o0 = (size_t)(row_base + i * 16) * D2 + col_base + j * 8;
            size_t o1 = o0 + 8 * D2;
            *(float2*)(out + o0) = make_float2(acc[i][j][0] + bj[j].x, acc[i][j][1] + bj[j].y);
            *(float2*)(out + o1) = make_float2(acc[i][j][2] + bj[j].x, acc[i][j][3] + bj[j].y);
        }
    }
}

// -----------------------------------------------------------------------------
extern "C" void kernel_launch(void* const* d_in, const int* in_sizes, int n_in,
                              void* d_out, int out_size) {
    const float*        x = (const float*)d_in[0];
    const float*        c = (const float*)d_in[1];
    const unsigned int* E = (const unsigned int*)d_in[2];
    const float*        W = (const float*)d_in[3];
    const float*        b = (const float*)d_in[4];
    float*            out = (float*)d_out;

    int nc = in_sizes[1];
    int M  = in_sizes[0] / D1;      // 8192

    __half *Wc, *X1;
    cudaGetSymbolAddress((void**)&Wc, g_Wc);
    cudaGetSymbolAddress((void**)&X1, g_X1);

    float scale = ALPHA / ((float)D1 * (float)D2);

    decode_E_kernel<<<1, 32>>>(E, nc);
    build_uv_kernel<<<dim3(D1, 2), 128>>>(c, nc, scale);

    cudaFuncSetAttribute(wsplit_kernel,
                         cudaFuncAttributeMaxDynamicSharedMemorySize, WS_SMEM);
    wsplit_kernel<<<dim3(D1 / 128, D2 / 128), 256, WS_SMEM>>>(W, Wc);

    size_t n4 = (size_t)M * D1 / 4;
    xcvt_kernel<<<(unsigned)((n4 + 255) / 256), 256>>>(x, X1, n4);

    cudaFuncSetAttribute(gemm_mma_kernel,
                         cudaFuncAttributeMaxDynamicSharedMemorySize, SMEM_MAIN);
    gemm_mma_kernel<<<dim3(D2 / BN, M / BM), 256, SMEM_MAIN>>>(
        X1, Wc, b, out);
}

// round 9
// speedup vs baseline: 9.4798x; 1.2070x over previous
#include <cuda_runtime.h>
#include <cuda_bf16.h>
#include <cuda_fp16.h>
#include <cstdint>

#define D1 4096
#define D2 4096
#define KTOT 4096
#define ALPHA 300.0f

// ---- main GEMM tiling ----
#define BM 256
#define BN 128
#define BK 64
#define STAGES 4
#define RSB 144                          // 128B row + 16B pad (16B-aligned)
#define A_OFF 0
#define B_OFF (BM * RSB)                 // 36864
#define STG_BYTES ((BM + BN) * RSB)      // 55296
#define SMEM_MAIN (STAGES * STG_BYTES)   // 221184
#define NCH (KTOT / BK)                  // 64

// ---- wsplit GEMM ----
#define KUV 256
#define RS2 528
#define WS_SMEM (2 * 128 * RS2)

// ---------------- device globals (scratch) -----------------------------------
__device__ int   g_rows[256];
__device__ int   g_cols[256];
__device__ __nv_bfloat16 g_Ub[D1 * KUV];
__device__ __nv_bfloat16 g_Vb[D2 * KUV];
__device__ __half g_Wc[(size_t)D2 * D1];
__device__ __half g_X1[(size_t)8192 * D1];

// ---------------- PTX helpers (portable, sm_80-era) ---------------------------
__device__ __forceinline__ uint32_t smem_u32(const void* p) {
    uint32_t a;
    asm("{ .reg .u64 t; cvta.to.shared.u64 t, %1; cvt.u32.u64 %0, t; }" : "=r"(a) : "l"(p));
    return a;
}
__device__ __forceinline__ void cpa16(uint32_t d, const void* s) {
    asm volatile("cp.async.cg.shared.global [%0], [%1], 16;"
                 :: "r"(d), "l"(__cvta_generic_to_global(s)) : "memory");
}
__device__ __forceinline__ void ldsm4(uint32_t* r, uint32_t addr) {
    asm volatile("ldmatrix.sync.aligned.m8n8.x4.shared.b16 {%0,%1,%2,%3}, [%4];"
                 : "=r"(r[0]), "=r"(r[1]), "=r"(r[2]), "=r"(r[3]) : "r"(addr));
}
__device__ __forceinline__ void mma_f16(float* c, const uint32_t* a, const uint32_t* b) {
    asm volatile(
        "mma.sync.aligned.m16n8k16.row.col.f32.f16.f16.f32 "
        "{%0,%1,%2,%3}, {%4,%5,%6,%7}, {%8,%9}, {%0,%1,%2,%3};"
        : "+f"(c[0]), "+f"(c[1]), "+f"(c[2]), "+f"(c[3])
        : "r"(a[0]), "r"(a[1]), "r"(a[2]), "r"(a[3]), "r"(b[0]), "r"(b[1]));
}
__device__ __forceinline__ void mma_bf16(float* c, const uint32_t* a, const uint32_t* b) {
    asm volatile(
        "mma.sync.aligned.m16n8k16.row.col.f32.bf16.bf16.f32 "
        "{%0,%1,%2,%3}, {%4,%5,%6,%7}, {%8,%9}, {%0,%1,%2,%3};"
        : "+f"(c[0]), "+f"(c[1]), "+f"(c[2]), "+f"(c[3])
        : "r"(a[0]), "r"(a[1]), "r"(a[2]), "r"(a[3]), "r"(b[0]), "r"(b[1]));
}

// ---------------- decode E (int32 or int64 storage) ---------------------------
__global__ void decode_E_kernel(const unsigned int* __restrict__ ew, int nc) {
    if (threadIdx.x != 0) return;
    unsigned int oddor = 0;
    for (int i = 0; i < nc; ++i) oddor |= ew[2 * i + 1];
    bool is64 = (oddor == 0u);
    for (int j = 0; j < nc; ++j) {
        if (is64) { g_rows[j] = (int)ew[4 * j]; g_cols[j] = (int)ew[4 * (nc + j)]; }
        else      { g_rows[j] = (int)ew[j];     g_cols[j] = (int)ew[nc + j]; }
    }
}

// ---------------- build U, V (bf16, zero-padded to KUV cols) -------------------
__global__ void build_uv_kernel(const float* __restrict__ c, int nc, float scale) {
    int k = blockIdx.x, j = threadIdx.x;
    bool isV = (blockIdx.y != 0);
    __nv_bfloat16* dst = (isV ? g_Vb : g_Ub) + (size_t)k * KUV;
    if (j < nc) {
        int f = isV ? g_cols[j] : g_rows[j];
        int p = (f * k) & (D1 - 1);
        float ang = (float)p * (6.2831853071795864769f / (float)D1);
        float sn, cs;
        sincosf(ang, &sn, &cs);
        if (isV) {
            dst[2 * j]     = __float2bfloat16(cs);
            dst[2 * j + 1] = __float2bfloat16(sn);
        } else {
            float a = c[j] * scale;
            dst[2 * j]     = __float2bfloat16(a * cs);
            dst[2 * j + 1] = __float2bfloat16(-a * sn);
        }
    } else {
        dst[2 * j]     = __float2bfloat16(0.f);
        dst[2 * j + 1] = __float2bfloat16(0.f);
    }
}

// ---------------- wsplit: Wc[l,k] = sum_t V[l,t]U[k,t] + W[l,k] -> fp16 --------
__global__ void __launch_bounds__(256, 1)
wsplit_kernel(const float* __restrict__ W, __half* __restrict__ Wc) {
    extern __shared__ __align__(128) char smem[];
    const uint32_t sb = smem_u32(smem);
    const uint32_t sbV = sb, sbU = sb + 128 * RS2;
    const int tid = threadIdx.x, lane = tid & 31, wid = tid >> 5;
    const int wm = wid & 3, wn = wid >> 2;
    const int l0 = blockIdx.y * 128, k0 = blockIdx.x * 128;

#pragma unroll
    for (int it = 0; it < 16; ++it) {
        int idx = it * 256 + tid;
        int row = idx >> 5, seg = idx & 31;
        uint32_t so = (uint32_t)(row * RS2 + seg * 16);
        cpa16(sbV + so, g_Vb + (size_t)(l0 + row) * KUV + seg * 8);
        cpa16(sbU + so, g_Ub + (size_t)(k0 + row) * KUV + seg * 8);
    }
    asm volatile("cp.async.commit_group;" ::: "memory");
    asm volatile("cp.async.wait_group 0;" ::: "memory");
    __syncthreads();

    const int a_row = (lane & 7) + ((lane >> 3) & 1) * 8;
    const int a_col = ((lane >> 4) & 1) * 8;
    const uint32_t a_off = (uint32_t)((wm * 32 + a_row) * RS2 + a_col * 2);
    const int b_row = (lane & 7) + ((lane >> 4) & 1) * 8;
    const int b_col = ((lane >> 3) & 1) * 8;
    const uint32_t b_off = (uint32_t)((wn * 64 + b_row) * RS2 + b_col * 2);

    float acc[2][8][4];
#pragma unroll
    for (int i = 0; i < 2; ++i)
#pragma unroll
        for (int j = 0; j < 8; ++j)
#pragma unroll
            for (int q = 0; q < 4; ++q) acc[i][j][q] = 0.f;

#pragma unroll
    for (int ks = 0; ks < KUV / 16; ++ks) {
        uint32_t a[2][4], b[8][2];
#pragma unroll
        for (int i = 0; i < 2; ++i)
            ldsm4(a[i], sbV + a_off + i * (16 * RS2) + ks * 32);
#pragma unroll
        for (int j = 0; j < 4; ++j) {
            uint32_t t4[4];
            ldsm4(t4, sbU + b_off + j * (16 * RS2) + ks * 32);
            b[2*j][0] = t4[0]; b[2*j][1] = t4[1];
            b[2*j+1][0] = t4[2]; b[2*j+1][1] = t4[3];
        }
#pragma unroll
        for (int i = 0; i < 2; ++i)
#pragma unroll
            for (int j = 0; j < 8; ++j)
                mma_bf16(acc[i][j], a[i], b[j]);
    }

    const int crow = l0 + wm * 32 + (lane >> 2);
    const int ccol = k0 + wn * 64 + 2 * (lane & 3);
#pragma unroll
    for (int i = 0; i < 2; ++i) {
#pragma unroll
        for (int j = 0; j < 8; ++j) {
#pragma unroll
            for (int h = 0; h < 2; ++h) {
                int r = crow + i * 16 + h * 8;
                size_t o = (size_t)r * D1 + ccol + j * 8;
                float2 w = *(const float2*)(W + o);
                *(__half2*)(Wc + o) = __halves2half2(
                    __float2half_rn(acc[i][j][2*h]   + w.x),
                    __float2half_rn(acc[i][j][2*h+1] + w.y));
            }
        }
    }
}

// ---------------- convert x -> fp16 -------------------------------------------
__global__ void xcvt_kernel(const float* __restrict__ s,
                            __half* __restrict__ d, size_t n4) {
    size_t i = blockIdx.x * (size_t)blockDim.x + threadIdx.x;
    if (i >= n4) return;
    float4 v = ((const float4*)s)[i];
    __half2 a = __halves2half2(__float2half_rn(v.x), __float2half_rn(v.y));
    __half2 b = __halves2half2(__float2half_rn(v.z), __float2half_rn(v.w));
    ((uint2*)d)[i] = make_uint2(*(uint32_t*)&a, *(uint32_t*)&b);
}

// ---------------- main GEMM: out = X1 Wc^T + b  (fp16, mma.sync) --------------
// CTA 256x128x64, 4-stage cp.async, 8 warps (4x2), warp tile 64x64.
// Fragments double-buffered across k16 steps AND across chunk boundaries:
// at kk==3 the next chunk's kk=0 fragments are loaded (wait_group 1 invariant
// guarantees chunk it+1 is resident), so the tensor pipe never stalls on the
// chunk-transition wait/sync/LDS chain.
__global__ void __launch_bounds__(256, 1)
gemm_mma_kernel(const __half* __restrict__ X1,
                const __half* __restrict__ Wc,
                const float* __restrict__ bias,
                float* __restrict__ out) {
    extern __shared__ __align__(128) char smem[];
    const uint32_t sb = smem_u32(smem);
    const int tid  = threadIdx.x;
    const int lane = tid & 31;
    const int wid  = tid >> 5;
    const int wm   = wid & 3;
    const int wn   = wid >> 2;
    const int m0   = blockIdx.y * BM;
    const int n0   = blockIdx.x * BN;

    auto load_chunk = [&](int stg, int chunk) {
        const uint32_t base = sb + stg * STG_BYTES;
        const int kc = chunk * BK;
#pragma unroll
        for (int it = 0; it < 8; ++it) {         // A: 256 rows x 8 segs of 16B
            int idx = it * 256 + tid;
            int row = idx >> 3, seg = idx & 7;
            uint32_t so = (uint32_t)(row * RSB + seg * 16);
            cpa16(base + A_OFF + so, X1 + (size_t)(m0 + row) * KTOT + kc + seg * 8);
        }
#pragma unroll
        for (int it = 0; it < 4; ++it) {         // B: 128 rows x 8 segs
            int idx = it * 256 + tid;
            int row = idx >> 3, seg = idx & 7;
            uint32_t so = (uint32_t)(row * RSB + seg * 16);
            cpa16(base + B_OFF + so, Wc + (size_t)(n0 + row) * KTOT + kc + seg * 8);
        }
    };

    const int a_row = (lane & 7) + ((lane >> 3) & 1) * 8;
    const int a_col = ((lane >> 4) & 1) * 8;
    const uint32_t a_off = (uint32_t)((wm * 64 + a_row) * RSB + a_col * 2);
    const int b_row = (lane & 7) + ((lane >> 4) & 1) * 8;
    const int b_col = ((lane >> 3) & 1) * 8;
    const uint32_t b_off = (uint32_t)((wn * 64 + b_row) * RSB + b_col * 2);

    uint32_t af[2][4][4], bf[2][8][2];
    auto ldfrag = [&](int buf, uint32_t st, int kk) {
#pragma unroll
        for (int i = 0; i < 4; ++i)
            ldsm4(af[buf][i], st + A_OFF + a_off + i * (16 * RSB) + kk * 32);
#pragma unroll
        for (int j = 0; j < 4; ++j) {
            uint32_t t4[4];
            ldsm4(t4, st + B_OFF + b_off + j * (16 * RSB) + kk * 32);
            bf[buf][2*j][0] = t4[0]; bf[buf][2*j][1] = t4[1];
            bf[buf][2*j+1][0] = t4[2]; bf[buf][2*j+1][1] = t4[3];
        }
    };

    float acc[4][8][4];
#pragma unroll
    for (int i = 0; i < 4; ++i)
#pragma unroll
        for (int j = 0; j < 8; ++j)
#pragma unroll
            for (int q = 0; q < 4; ++q) acc[i][j][q] = 0.f;

    // prologue: chunks 0..2 in flight; chunks 0,1 guaranteed resident
#pragma unroll
    for (int s = 0; s < 3; ++s) {
        load_chunk(s, s);
        asm volatile("cp.async.commit_group;" ::: "memory");
    }
    asm volatile("cp.async.wait_group 1;" ::: "memory");
    __syncthreads();
    ldfrag(0, sb, 0);

    for (int it = 0; it < NCH; ++it) {
        const uint32_t st  = sb + (it & 3) * STG_BYTES;
        const uint32_t stn = sb + ((it + 1) & 3) * STG_BYTES;
#pragma unroll
        for (int kk = 0; kk < 4; ++kk) {
            const int cur = kk & 1;
            if (kk < 3)            ldfrag(cur ^ 1, st, kk + 1);
            else if (it + 1 < NCH) ldfrag(cur ^ 1, stn, 0);   // next chunk kk=0
#pragma unroll
            for (int i = 0; i < 4; ++i)
#pragma unroll
                for (int j = 0; j < 8; ++j)
                    mma_f16(acc[i][j], af[cur][i], bf[cur][j]);
        }
        // all warps done reading stage (it&3); safe to overwrite it next time
        __syncthreads();
        if (it + 3 < NCH) load_chunk((it + 3) & 3, it + 3);
        asm volatile("cp.async.commit_group;" ::: "memory");
        // ensure chunk it+2 resident -> invariant for next iter's kk==3 prefetch
        asm volatile("cp.async.wait_group 1;" ::: "memory");
    }

    // epilogue
    const int col_base = n0 + wn * 64 + 2 * (lane & 3);
    float2 bj[8];
#pragma unroll
    for (int j = 0; j < 8; ++j) {
        bj[j].x = __ldg(bias + col_base + j * 8);
        bj[j].y = __ldg(bias + col_base + j * 8 + 1);
    }
    const int row_base = m0 + wm * 64 + (lane >> 2);
#pragma unroll
    for (int i = 0; i < 4; ++i) {
#pragma unroll
        for (int j = 0; j < 8; ++j) {
            size_t o0 = (size_t)(row_base + i * 16) * D2 + col_base + j * 8;
            size_t o1 = o0 + 8 * D2;
            *(float2*)(out + o0) = make_float2(acc[i][j][0] + bj[j].x, acc[i][j][1] + bj[j].y);
            *(float2*)(out + o1) = make_float2(acc[i][j][2] + bj[j].x, acc[i][j][3] + bj[j].y);
        }
    }
}

// -----------------------------------------------------------------------------
extern "C" void kernel_launch(void* const* d_in, const int* in_sizes, int n_in,
                              void* d_out, int out_size) {
    const float*        x = (const float*)d_in[0];
    const float*        c = (const float*)d_in[1];
    const unsigned int* E = (const unsigned int*)d_in[2];
    const float*        W = (const float*)d_in[3];
    const float*        b = (const float*)d_in[4];
    float*            out = (float*)d_out;

    int nc = in_sizes[1];
    int M  = in_sizes[0] / D1;      // 8192

    __half *Wc, *X1;
    cudaGetSymbolAddress((void**)&Wc, g_Wc);
    cudaGetSymbolAddress((void**)&X1, g_X1);

    float scale = ALPHA / ((float)D1 * (float)D2);

    decode_E_kernel<<<1, 32>>>(E, nc);
    build_uv_kernel<<<dim3(D1, 2), 128>>>(c, nc, scale);

    cudaFuncSetAttribute(wsplit_kernel,
                         cudaFuncAttributeMaxDynamicSharedMemorySize, WS_SMEM);
    wsplit_kernel<<<dim3(D1 / 128, D2 / 128), 256, WS_SMEM>>>(W, Wc);

    size_t n4 = (size_t)M * D1 / 4;
    xcvt_kernel<<<(unsigned)((n4 + 255) / 256), 256>>>(x, X1, n4);

    cudaFuncSetAttribute(gemm_mma_kernel,
                         cudaFuncAttributeMaxDynamicSharedMemorySize, SMEM_MAIN);
    gemm_mma_kernel<<<dim3(D2 / BN, M / BM), 256, SMEM_MAIN>>>(
        X1, Wc, b, out);
}

// round 10
// speedup vs baseline: 10.2882x; 1.0853x over previous
#include <cuda_runtime.h>
#include <cuda_bf16.h>
#include <cuda_fp16.h>
#include <cstdint>

#define D1 4096
#define D2 4096
#define KTOT 4096
#define ALPHA 300.0f

// ---- main GEMM tiling ----
#define BM 256
#define BN 128
#define BK 64
#define STAGES 4
#define RSB 144                          // 128B row + 16B pad (16B-aligned)
#define A_OFF 0
#define B_OFF (BM * RSB)                 // 36864
#define STG_BYTES ((BM + BN) * RSB)      // 55296
#define SMEM_MAIN (STAGES * STG_BYTES)   // 221184
#define NCH (KTOT / BK)                  // 64

// ---- wsplit GEMM ----
#define KUV 256
#define RS2 528
#define WS_SMEM (2 * 128 * RS2)

// ---------------- device globals (scratch) -----------------------------------
__device__ __nv_bfloat16 g_Ub[D1 * KUV];
__device__ __nv_bfloat16 g_Vb[D2 * KUV];
__device__ __half g_Wc[(size_t)D2 * D1];
__device__ __half g_X1[(size_t)8192 * D1];

// ---------------- PTX helpers (portable, sm_80-era) ---------------------------
__device__ __forceinline__ uint32_t smem_u32(const void* p) {
    uint32_t a;
    asm("{ .reg .u64 t; cvta.to.shared.u64 t, %1; cvt.u32.u64 %0, t; }" : "=r"(a) : "l"(p));
    return a;
}
__device__ __forceinline__ void cpa16(uint32_t d, const void* s) {
    asm volatile("cp.async.cg.shared.global [%0], [%1], 16;"
                 :: "r"(d), "l"(__cvta_generic_to_global(s)) : "memory");
}
__device__ __forceinline__ void ldsm4(uint32_t* r, uint32_t addr) {
    asm volatile("ldmatrix.sync.aligned.m8n8.x4.shared.b16 {%0,%1,%2,%3}, [%4];"
                 : "=r"(r[0]), "=r"(r[1]), "=r"(r[2]), "=r"(r[3]) : "r"(addr));
}
__device__ __forceinline__ void mma_f16(float* c, const uint32_t* a, const uint32_t* b) {
    asm volatile(
        "mma.sync.aligned.m16n8k16.row.col.f32.f16.f16.f32 "
        "{%0,%1,%2,%3}, {%4,%5,%6,%7}, {%8,%9}, {%0,%1,%2,%3};"
        : "+f"(c[0]), "+f"(c[1]), "+f"(c[2]), "+f"(c[3])
        : "r"(a[0]), "r"(a[1]), "r"(a[2]), "r"(a[3]), "r"(b[0]), "r"(b[1]));
}
__device__ __forceinline__ void mma_bf16(float* c, const uint32_t* a, const uint32_t* b) {
    asm volatile(
        "mma.sync.aligned.m16n8k16.row.col.f32.bf16.bf16.f32 "
        "{%0,%1,%2,%3}, {%4,%5,%6,%7}, {%8,%9}, {%0,%1,%2,%3};"
        : "+f"(c[0]), "+f"(c[1]), "+f"(c[2]), "+f"(c[3])
        : "r"(a[0]), "r"(a[1]), "r"(a[2]), "r"(a[3]), "r"(b[0]), "r"(b[1]));
}

// ---------------- build U, V (decode of E fused in) ----------------------------
// E storage may be int64 (all high words of values <4096 are 0) or int32.
__global__ void build_uv_kernel(const float* __restrict__ c,
                                const unsigned int* __restrict__ ew,
                                int nc, float scale) {
    int k = blockIdx.x, j = threadIdx.x;
    bool isV = (blockIdx.y != 0);
    // block-wide detection: OR of all odd 32-bit words of the first nc elements
    unsigned int myw = (j < nc) ? ew[2 * j + 1] : 0u;
    bool is64 = (__syncthreads_or((int)(myw != 0u)) == 0);
    __nv_bfloat16* dst = (isV ? g_Vb : g_Ub) + (size_t)k * KUV;
    if (j < nc) {
        int f;
        if (is64) f = (int)(isV ? ew[4 * (nc + j)] : ew[4 * j]);
        else      f = (int)(isV ? ew[nc + j]       : ew[j]);
        int p = (f * k) & (D1 - 1);
        float ang = (float)p * (6.2831853071795864769f / (float)D1);
        float sn, cs;
        sincosf(ang, &sn, &cs);
        if (isV) {
            dst[2 * j]     = __float2bfloat16(cs);
            dst[2 * j + 1] = __float2bfloat16(sn);
        } else {
            float a = c[j] * scale;
            dst[2 * j]     = __float2bfloat16(a * cs);
            dst[2 * j + 1] = __float2bfloat16(-a * sn);
        }
    } else {
        dst[2 * j]     = __float2bfloat16(0.f);
        dst[2 * j + 1] = __float2bfloat16(0.f);
    }
}

// ---------------- wsplit: Wc[l,k] = sum_t V[l,t]U[k,t] + W[l,k] -> fp16 --------
__global__ void __launch_bounds__(256, 1)
wsplit_kernel(const float* __restrict__ W, __half* __restrict__ Wc) {
    extern __shared__ __align__(128) char smem[];
    const uint32_t sb = smem_u32(smem);
    const uint32_t sbV = sb, sbU = sb + 128 * RS2;
    const int tid = threadIdx.x, lane = tid & 31, wid = tid >> 5;
    const int wm = wid & 3, wn = wid >> 2;
    const int l0 = blockIdx.y * 128, k0 = blockIdx.x * 128;

#pragma unroll
    for (int it = 0; it < 16; ++it) {
        int idx = it * 256 + tid;
        int row = idx >> 5, seg = idx & 31;
        uint32_t so = (uint32_t)(row * RS2 + seg * 16);
        cpa16(sbV + so, g_Vb + (size_t)(l0 + row) * KUV + seg * 8);
        cpa16(sbU + so, g_Ub + (size_t)(k0 + row) * KUV + seg * 8);
    }
    asm volatile("cp.async.commit_group;" ::: "memory");
    asm volatile("cp.async.wait_group 0;" ::: "memory");
    __syncthreads();

    const int a_row = (lane & 7) + ((lane >> 3) & 1) * 8;
    const int a_col = ((lane >> 4) & 1) * 8;
    const uint32_t a_off = (uint32_t)((wm * 32 + a_row) * RS2 + a_col * 2);
    const int b_row = (lane & 7) + ((lane >> 4) & 1) * 8;
    const int b_col = ((lane >> 3) & 1) * 8;
    const uint32_t b_off = (uint32_t)((wn * 64 + b_row) * RS2 + b_col * 2);

    float acc[2][8][4];
#pragma unroll
    for (int i = 0; i < 2; ++i)
#pragma unroll
        for (int j = 0; j < 8; ++j)
#pragma unroll
            for (int q = 0; q < 4; ++q) acc[i][j][q] = 0.f;

#pragma unroll
    for (int ks = 0; ks < KUV / 16; ++ks) {
        uint32_t a[2][4], b[8][2];
#pragma unroll
        for (int i = 0; i < 2; ++i)
            ldsm4(a[i], sbV + a_off + i * (16 * RS2) + ks * 32);
#pragma unroll
        for (int j = 0; j < 4; ++j) {
            uint32_t t4[4];
            ldsm4(t4, sbU + b_off + j * (16 * RS2) + ks * 32);
            b[2*j][0] = t4[0]; b[2*j][1] = t4[1];
            b[2*j+1][0] = t4[2]; b[2*j+1][1] = t4[3];
        }
#pragma unroll
        for (int i = 0; i < 2; ++i)
#pragma unroll
            for (int j = 0; j < 8; ++j)
                mma_bf16(acc[i][j], a[i], b[j]);
    }

    const int crow = l0 + wm * 32 + (lane >> 2);
    const int ccol = k0 + wn * 64 + 2 * (lane & 3);
#pragma unroll
    for (int i = 0; i < 2; ++i) {
#pragma unroll
        for (int j = 0; j < 8; ++j) {
#pragma unroll
            for (int h = 0; h < 2; ++h) {
                int r = crow + i * 16 + h * 8;
                size_t o = (size_t)r * D1 + ccol + j * 8;
                float2 w = *(const float2*)(W + o);
                *(__half2*)(Wc + o) = __halves2half2(
                    __float2half_rn(acc[i][j][2*h]   + w.x),
                    __float2half_rn(acc[i][j][2*h+1] + w.y));
            }
        }
    }
}

// ---------------- convert x -> fp16 -------------------------------------------
__global__ void xcvt_kernel(const float* __restrict__ s,
                            __half* __restrict__ d, size_t n4) {
    size_t i = blockIdx.x * (size_t)blockDim.x + threadIdx.x;
    if (i >= n4) return;
    float4 v = ((const float4*)s)[i];
    __half2 a = __halves2half2(__float2half_rn(v.x), __float2half_rn(v.y));
    __half2 b = __halves2half2(__float2half_rn(v.z), __float2half_rn(v.w));
    ((uint2*)d)[i] = make_uint2(*(uint32_t*)&a, *(uint32_t*)&b);
}

// ---------------- main GEMM: out = X1 Wc^T + b  (fp16, mma.sync) --------------
// CTA 256x128x64, 4-stage cp.async, 8 warps (4x2), warp tile 64x64.
// Fragments double-buffered across k16 steps AND chunk boundaries; chunk loads
// issued at the top of each iteration (right after the barrier) for earlier
// latency hiding.
__global__ void __launch_bounds__(256, 1)
gemm_mma_kernel(const __half* __restrict__ X1,
                const __half* __restrict__ Wc,
                const float* __restrict__ bias,
                float* __restrict__ out) {
    extern __shared__ __align__(128) char smem[];
    const uint32_t sb = smem_u32(smem);
    const int tid  = threadIdx.x;
    const int lane = tid & 31;
    const int wid  = tid >> 5;
    const int wm   = wid & 3;
    const int wn   = wid >> 2;
    const int m0   = blockIdx.y * BM;
    const int n0   = blockIdx.x * BN;

    auto load_chunk = [&](int stg, int chunk) {
        const uint32_t base = sb + stg * STG_BYTES;
        const int kc = chunk * BK;
#pragma unroll
        for (int it = 0; it < 8; ++it) {         // A: 256 rows x 8 segs of 16B
            int idx = it * 256 + tid;
            int row = idx >> 3, seg = idx & 7;
            uint32_t so = (uint32_t)(row * RSB + seg * 16);
            cpa16(base + A_OFF + so, X1 + (size_t)(m0 + row) * KTOT + kc + seg * 8);
        }
#pragma unroll
        for (int it = 0; it < 4; ++it) {         // B: 128 rows x 8 segs
            int idx = it * 256 + tid;
            int row = idx >> 3, seg = idx & 7;
            uint32_t so = (uint32_t)(row * RSB + seg * 16);
            cpa16(base + B_OFF + so, Wc + (size_t)(n0 + row) * KTOT + kc + seg * 8);
        }
    };

    const int a_row = (lane & 7) + ((lane >> 3) & 1) * 8;
    const int a_col = ((lane >> 4) & 1) * 8;
    const uint32_t a_off = (uint32_t)((wm * 64 + a_row) * RSB + a_col * 2);
    const int b_row = (lane & 7) + ((lane >> 4) & 1) * 8;
    const int b_col = ((lane >> 3) & 1) * 8;
    const uint32_t b_off = (uint32_t)((wn * 64 + b_row) * RSB + b_col * 2);

    uint32_t af[2][4][4], bf[2][8][2];
    auto ldfrag = [&](int buf, uint32_t st, int kk) {
#pragma unroll
        for (int i = 0; i < 4; ++i)
            ldsm4(af[buf][i], st + A_OFF + a_off + i * (16 * RSB) + kk * 32);
#pragma unroll
        for (int j = 0; j < 4; ++j) {
            uint32_t t4[4];
            ldsm4(t4, st + B_OFF + b_off + j * (16 * RSB) + kk * 32);
            bf[buf][2*j][0] = t4[0]; bf[buf][2*j][1] = t4[1];
            bf[buf][2*j+1][0] = t4[2]; bf[buf][2*j+1][1] = t4[3];
        }
    };

    float acc[4][8][4];
#pragma unroll
    for (int i = 0; i < 4; ++i)
#pragma unroll
        for (int j = 0; j < 8; ++j)
#pragma unroll
            for (int q = 0; q < 4; ++q) acc[i][j][q] = 0.f;

    // prologue: chunks 0..2 in flight; chunks 0,1 guaranteed resident
#pragma unroll
    for (int s = 0; s < 3; ++s) {
        load_chunk(s, s);
        asm volatile("cp.async.commit_group;" ::: "memory");
    }
    asm volatile("cp.async.wait_group 1;" ::: "memory");
    __syncthreads();
    ldfrag(0, sb, 0);

    for (int it = 0; it < NCH; ++it) {
        const uint32_t st  = sb + (it & 3) * STG_BYTES;
        const uint32_t stn = sb + ((it + 1) & 3) * STG_BYTES;

        // stage (it+3)&3 == (it-1)&3 was last read in iter it-1; the barrier at
        // the end of iter it-1 (or the prologue sync) makes its overwrite safe.
        if (it + 3 < NCH) load_chunk((it + 3) & 3, it + 3);
        asm volatile("cp.async.commit_group;" ::: "memory");

#pragma unroll
        for (int kk = 0; kk < 4; ++kk) {
            const int cur = kk & 1;
            if (kk < 3)            ldfrag(cur ^ 1, st, kk + 1);
            else if (it + 1 < NCH) ldfrag(cur ^ 1, stn, 0);   // next chunk kk=0
#pragma unroll
            for (int i = 0; i < 4; ++i)
#pragma unroll
                for (int j = 0; j < 8; ++j)
                    mma_f16(acc[i][j], af[cur][i], bf[cur][j]);
        }
        // ensure chunk it+2 resident -> invariant for next iter's kk==3 prefetch
        asm volatile("cp.async.wait_group 1;" ::: "memory");
        __syncthreads();
    }

    // epilogue
    const int col_base = n0 + wn * 64 + 2 * (lane & 3);
    float2 bj[8];
#pragma unroll
    for (int j = 0; j < 8; ++j) {
        bj[j].x = __ldg(bias + col_base + j * 8);
        bj[j].y = __ldg(bias + col_base + j * 8 + 1);
    }
    const int row_base = m0 + wm * 64 + (lane >> 2);
#pragma unroll
    for (int i = 0; i < 4; ++i) {
#pragma unroll
        for (int j = 0; j < 8; ++j) {
            size_t o0 = (size_t)(row_base + i * 16) * D2 + col_base + j * 8;
            size_t o1 = o0 + 8 * D2;
            *(float2*)(out + o0) = make_float2(acc[i][j][0] + bj[j].x, acc[i][j][1] + bj[j].y);
            *(float2*)(out + o1) = make_float2(acc[i][j][2] + bj[j].x, acc[i][j][3] + bj[j].y);
        }
    }
}

// -----------------------------------------------------------------------------
extern "C" void kernel_launch(void* const* d_in, const int* in_sizes, int n_in,
                              void* d_out, int out_size) {
    const float*        x = (const float*)d_in[0];
    const float*        c = (const float*)d_in[1];
    const unsigned int* E = (const unsigned int*)d_in[2];
    const float*        W = (const float*)d_in[3];
    const float*        b = (const float*)d_in[4];
    float*            out = (float*)d_out;

    int nc = in_sizes[1];
    int M  = in_sizes[0] / D1;      // 8192

    __half *Wc, *X1;
    cudaGetSymbolAddress((void**)&Wc, g_Wc);
    cudaGetSymbolAddress((void**)&X1, g_X1);

    float scale = ALPHA / ((float)D1 * (float)D2);

    // launch order matters for ncu visibility: gemm is the 4th (profiled) launch
    build_uv_kernel<<<dim3(D1, 2), 128>>>(c, E, nc, scale);

    cudaFuncSetAttribute(wsplit_kernel,
                         cudaFuncAttributeMaxDynamicSharedMemorySize, WS_SMEM);
    wsplit_kernel<<<dim3(D1 / 128, D2 / 128), 256, WS_SMEM>>>(W, Wc);

    size_t n4 = (size_t)M * D1 / 4;
    xcvt_kernel<<<(unsigned)((n4 + 255) / 256), 256>>>(x, X1, n4);

    cudaFuncSetAttribute(gemm_mma_kernel,
                         cudaFuncAttributeMaxDynamicSharedMemorySize, SMEM_MAIN);
    gemm_mma_kernel<<<dim3(D2 / BN, M / BM), 256, SMEM_MAIN>>>(
        X1, Wc, b, out);
}